// round 1
// baseline (speedup 1.0000x reference)
#include <cuda_runtime.h>
#include <math.h>

// Problem constants
#define BATCH 4
#define LQQ   2048
#define LKK   2048
#define DMODEL 1024
#define NHEAD 16
#define DHEAD 64

// Scratch (static device arrays -- no runtime allocation allowed)
__device__ float g_qln [BATCH * LQQ * DMODEL];
__device__ float g_kvln[BATCH * LKK * DMODEL];
__device__ float g_q   [BATCH * LQQ * DMODEL];
__device__ float g_k   [BATCH * LKK * DMODEL];
__device__ float g_v   [BATCH * LKK * DMODEL];
__device__ float g_ao  [BATCH * LQQ * DMODEL];
__device__ int   g_mask_mode; // 0=uint8, 1=int32, 2=float32

// ---------------------------------------------------------------------------
// Mask dtype detection: key_padding_mask is a bool array in the reference;
// the harness may hand it to us as u8 / i32 / f32. Values are only 0/1 so the
// byte pattern identifies the dtype. Reads only the first 8192 bytes (safe
// for all three interpretations).
// ---------------------------------------------------------------------------
__global__ void detect_mask_kernel(const unsigned char* __restrict__ m) {
    __shared__ int nz[4];
    if (threadIdx.x < 4) nz[threadIdx.x] = 0;
    __syncthreads();
    int loc = 0;
    for (int i = threadIdx.x; i < 8192; i += blockDim.x)
        if (m[i]) loc = 1;
    if (loc) atomicOr(&nz[threadIdx.x & 3], 1);
    __syncthreads();
    if (threadIdx.x == 0) {
        int mode;
        int tot = nz[0] | nz[1] | nz[2] | nz[3];
        if (!tot)                         mode = 0; // all zero: u8 read is safe/correct
        else if (!(nz[1] | nz[2] | nz[3])) mode = 1; // only byte0 nonzero -> int32 (LE)
        else if (!(nz[0] | nz[1]))         mode = 2; // 0x3F80 0000 pattern -> float32
        else                               mode = 0; // scattered -> uint8/bool
        g_mask_mode = mode;
    }
}

// ---------------------------------------------------------------------------
// LayerNorm: one block per row of 1024, 256 threads, float4 paths.
// ---------------------------------------------------------------------------
__global__ void ln_kernel(const float* __restrict__ x,
                          const float* __restrict__ w,
                          const float* __restrict__ bia,
                          float* __restrict__ out) {
    int row = blockIdx.x;
    int tid = threadIdx.x;
    const float4* xr = reinterpret_cast<const float4*>(x + (size_t)row * DMODEL);
    float4 a = xr[tid];
    float s  = a.x + a.y + a.z + a.w;
    float ss = a.x * a.x + a.y * a.y + a.z * a.z + a.w * a.w;

    __shared__ float rs[8], rss[8], stats[2];
    #pragma unroll
    for (int o = 16; o; o >>= 1) {
        s  += __shfl_xor_sync(0xffffffffu, s,  o);
        ss += __shfl_xor_sync(0xffffffffu, ss, o);
    }
    int wid = tid >> 5, lane = tid & 31;
    if (!lane) { rs[wid] = s; rss[wid] = ss; }
    __syncthreads();
    if (tid == 0) {
        float S = 0.f, SS = 0.f;
        #pragma unroll
        for (int i = 0; i < 8; i++) { S += rs[i]; SS += rss[i]; }
        float mean = S * (1.0f / DMODEL);
        float var  = SS * (1.0f / DMODEL) - mean * mean;
        stats[0] = mean;
        stats[1] = rsqrtf(var + 1e-5f);
    }
    __syncthreads();
    float mean = stats[0], rstd = stats[1];
    float4 wv = reinterpret_cast<const float4*>(w)[tid];
    float4 bv = reinterpret_cast<const float4*>(bia)[tid];
    float4 o;
    o.x = (a.x - mean) * rstd * wv.x + bv.x;
    o.y = (a.y - mean) * rstd * wv.y + bv.y;
    o.z = (a.z - mean) * rstd * wv.z + bv.z;
    o.w = (a.w - mean) * rstd * wv.w + bv.w;
    reinterpret_cast<float4*>(out + (size_t)row * DMODEL)[tid] = o;
}

// ---------------------------------------------------------------------------
// SGEMM: C[M,N] = A[M,K] @ B[K,N], row-major, all dims multiples of tile.
// 64x64x16 tiles, 256 threads, 4x4 register blocking, float4 smem reads.
// ---------------------------------------------------------------------------
#define GBM 64
#define GBN 64
#define GBK 16
#define AST 68  // padded stride (bytes: 272, 16B-aligned, avoids worst conflicts)

__global__ void sgemm_kernel(const float* __restrict__ A,
                             const float* __restrict__ Bm,
                             float* __restrict__ C,
                             int M, int N, int K) {
    __shared__ float As[GBK][AST];
    __shared__ float Bs[GBK][GBN];
    int tid = threadIdx.x;
    int m0 = blockIdx.y * GBM;
    int n0 = blockIdx.x * GBN;
    int ty = tid >> 4, tx = tid & 15;

    float acc[4][4] = {};

    int arow  = tid >> 2;        // 0..63
    int acol4 = (tid & 3) << 2;  // 0,4,8,12
    int brow  = tid >> 4;        // 0..15
    int bcol4 = (tid & 15) << 2; // 0..60

    const float* Aptr = A + (size_t)(m0 + arow) * K + acol4;
    const float* Bptr = Bm + (size_t)brow * N + n0 + bcol4;

    for (int k0 = 0; k0 < K; k0 += GBK) {
        float4 av = *reinterpret_cast<const float4*>(Aptr + k0);
        float4 bv = *reinterpret_cast<const float4*>(Bptr + (size_t)k0 * N);
        As[acol4 + 0][arow] = av.x;
        As[acol4 + 1][arow] = av.y;
        As[acol4 + 2][arow] = av.z;
        As[acol4 + 3][arow] = av.w;
        *reinterpret_cast<float4*>(&Bs[brow][bcol4]) = bv;
        __syncthreads();
        #pragma unroll
        for (int kk = 0; kk < GBK; kk++) {
            float4 a4 = *reinterpret_cast<const float4*>(&As[kk][ty << 2]);
            float4 b4 = *reinterpret_cast<const float4*>(&Bs[kk][tx << 2]);
            float ar[4] = {a4.x, a4.y, a4.z, a4.w};
            float br[4] = {b4.x, b4.y, b4.z, b4.w};
            #pragma unroll
            for (int i = 0; i < 4; i++)
                #pragma unroll
                for (int j = 0; j < 4; j++)
                    acc[i][j] += ar[i] * br[j];
        }
        __syncthreads();
    }
    #pragma unroll
    for (int i = 0; i < 4; i++) {
        float4 o = make_float4(acc[i][0], acc[i][1], acc[i][2], acc[i][3]);
        *reinterpret_cast<float4*>(C + (size_t)(m0 + (ty << 2) + i) * N + n0 + (tx << 2)) = o;
    }
}

// ---------------------------------------------------------------------------
// L2 norm over contiguous 64-float head vectors: one warp per vector.
// ---------------------------------------------------------------------------
__global__ void l2norm_kernel(float* __restrict__ d, int nvec) {
    int idx  = blockIdx.x * blockDim.x + threadIdx.x;
    int warp = idx >> 5;
    int lane = idx & 31;
    if (warp >= nvec) return;
    float2* p = reinterpret_cast<float2*>(d) + (size_t)warp * 32 + lane;
    float2 v = *p;
    float ss = v.x * v.x + v.y * v.y;
    #pragma unroll
    for (int o = 16; o; o >>= 1) ss += __shfl_xor_sync(0xffffffffu, ss, o);
    float sc = 1.0f / fmaxf(sqrtf(ss), 1e-12f);
    v.x *= sc; v.y *= sc;
    *p = v;
}

// ---------------------------------------------------------------------------
// Flash attention (fp32): grid (LQ/64, H, B), 256 threads.
// 64 q-rows per block, streamed 64-key tiles, online softmax, acc in regs.
// ---------------------------------------------------------------------------
__global__ void attn_kernel(const float* __restrict__ Q,
                            const float* __restrict__ Kp,
                            const float* __restrict__ V,
                            const void*  __restrict__ mask,
                            const float* __restrict__ tau_p,
                            float* __restrict__ O) {
    extern __shared__ float sm[];
    const int ST = 65;
    float* Qs    = sm;                 // 64*65
    float* Ks    = Qs + 64 * ST;
    float* Vs    = Ks + 64 * ST;
    float* Sb    = Vs + 64 * ST;
    float* mrow  = Sb + 64 * ST;       // 64
    float* lrow  = mrow + 64;
    float* corr  = lrow + 64;
    float* maskS = corr + 64;

    int tid = threadIdx.x;
    int q0 = blockIdx.x * 64;
    int h  = blockIdx.y;
    int b  = blockIdx.z;
    int ty = tid >> 4, tx = tid & 15;
    int r0 = ty << 2, c0 = tx << 2;

    float inv_tau = 1.0f / (*tau_p + 1e-6f);
    int mode = g_mask_mode;
    const unsigned char* m8  = (const unsigned char*)mask;
    const int*           m32 = (const int*)mask;
    const float*         mf  = (const float*)mask;

    #pragma unroll
    for (int i = 0; i < 16; i++) {
        int idx = tid + i * 256;
        int r = idx >> 6, d = idx & 63;
        Qs[r * ST + d] = Q[((size_t)(b * LQQ + q0 + r)) * DMODEL + h * DHEAD + d];
    }
    if (tid < 64) { mrow[tid] = -1e30f; lrow[tid] = 0.f; }

    float acc[4][4] = {};

    for (int kt = 0; kt < LKK / 64; kt++) {
        int k0 = kt * 64;
        __syncthreads();
        #pragma unroll
        for (int i = 0; i < 16; i++) {
            int idx = tid + i * 256;
            int r = idx >> 6, d = idx & 63;
            size_t g = ((size_t)(b * LKK + k0 + r)) * DMODEL + h * DHEAD + d;
            Ks[r * ST + d] = Kp[g];
            Vs[r * ST + d] = V[g];
        }
        if (tid < 64) {
            int km = b * LKK + k0 + tid;
            bool mm = (mode == 0) ? (m8[km] != 0)
                    : (mode == 1) ? (m32[km] != 0)
                                  : (mf[km] != 0.f);
            maskS[tid] = mm ? 1.f : 0.f;
        }
        __syncthreads();

        // scores S = (Q . K^T) * inv_tau, masked -> -1e30
        float s[4][4] = {};
        #pragma unroll
        for (int kk = 0; kk < 64; kk++) {
            float a[4], bb[4];
            #pragma unroll
            for (int i = 0; i < 4; i++) a[i]  = Qs[(r0 + i) * ST + kk];
            #pragma unroll
            for (int j = 0; j < 4; j++) bb[j] = Ks[(c0 + j) * ST + kk];
            #pragma unroll
            for (int i = 0; i < 4; i++)
                #pragma unroll
                for (int j = 0; j < 4; j++)
                    s[i][j] += a[i] * bb[j];
        }
        #pragma unroll
        for (int j = 0; j < 4; j++) {
            bool mm = (maskS[c0 + j] != 0.f);
            #pragma unroll
            for (int i = 0; i < 4; i++) {
                float v2 = mm ? -1e30f : s[i][j] * inv_tau;
                Sb[(r0 + i) * ST + c0 + j] = v2;
            }
        }
        __syncthreads();

        // online softmax update per row (64 threads, one row each)
        if (tid < 64) {
            int r = tid;
            float mold = mrow[r];
            float mx = mold;
            for (int c = 0; c < 64; c++) mx = fmaxf(mx, Sb[r * ST + c]);
            float cr = __expf(mold - mx);
            float sum = 0.f;
            for (int c = 0; c < 64; c++) {
                float sv = Sb[r * ST + c];
                float e = (sv <= -5e29f) ? 0.f : __expf(sv - mx);
                Sb[r * ST + c] = e;
                sum += e;
            }
            corr[r] = cr;
            lrow[r] = lrow[r] * cr + sum;
            mrow[r] = mx;
        }
        __syncthreads();

        // acc = acc * corr + P @ V
        float cr4[4];
        #pragma unroll
        for (int i = 0; i < 4; i++) cr4[i] = corr[r0 + i];
        #pragma unroll
        for (int i = 0; i < 4; i++)
            #pragma unroll
            for (int j = 0; j < 4; j++) acc[i][j] *= cr4[i];
        #pragma unroll
        for (int kk = 0; kk < 64; kk++) {
            float p[4], vv[4];
            #pragma unroll
            for (int i = 0; i < 4; i++) p[i]  = Sb[(r0 + i) * ST + kk];
            #pragma unroll
            for (int j = 0; j < 4; j++) vv[j] = Vs[kk * ST + c0 + j];
            #pragma unroll
            for (int i = 0; i < 4; i++)
                #pragma unroll
                for (int j = 0; j < 4; j++)
                    acc[i][j] += p[i] * vv[j];
        }
    }
    __syncthreads();
    #pragma unroll
    for (int i = 0; i < 4; i++) {
        float linv = 1.0f / lrow[r0 + i];
        #pragma unroll
        for (int j = 0; j < 4; j++) {
            O[((size_t)(b * LQQ + q0 + r0 + i)) * DMODEL + h * DHEAD + c0 + j] =
                acc[i][j] * linv;
        }
    }
}

// ---------------------------------------------------------------------------
// Launcher
// ---------------------------------------------------------------------------
extern "C" void kernel_launch(void* const* d_in, const int* in_sizes, int n_in,
                              void* d_out, int out_size) {
    const float* x     = (const float*)d_in[0];
    const float* ctx   = (const float*)d_in[1];
    const void*  mask  = d_in[2];
    const float* lnqw  = (const float*)d_in[3];
    const float* lnqb  = (const float*)d_in[4];
    const float* lncw  = (const float*)d_in[5];
    const float* lncb  = (const float*)d_in[6];
    const float* Wq    = (const float*)d_in[7];
    const float* Wk    = (const float*)d_in[8];
    const float* Wv    = (const float*)d_in[9];
    const float* Wo    = (const float*)d_in[10];
    const float* taup  = (const float*)d_in[11];
    float* out = (float*)d_out;

    float *qln, *kvln, *q, *k, *v, *ao;
    cudaGetSymbolAddress((void**)&qln,  g_qln);
    cudaGetSymbolAddress((void**)&kvln, g_kvln);
    cudaGetSymbolAddress((void**)&q,    g_q);
    cudaGetSymbolAddress((void**)&k,    g_k);
    cudaGetSymbolAddress((void**)&v,    g_v);
    cudaGetSymbolAddress((void**)&ao,   g_ao);

    const int smem_attn = (4 * 64 * 65 + 4 * 64) * (int)sizeof(float); // 67584
    cudaFuncSetAttribute(attn_kernel, cudaFuncAttributeMaxDynamicSharedMemorySize, smem_attn);

    detect_mask_kernel<<<1, 256>>>((const unsigned char*)mask);

    ln_kernel<<<BATCH * LQQ, 256>>>(x,   lnqw, lnqb, qln);
    ln_kernel<<<BATCH * LKK, 256>>>(ctx, lncw, lncb, kvln);

    dim3 gg(DMODEL / GBN, (BATCH * LQQ) / GBM);
    sgemm_kernel<<<gg, 256>>>(qln,  Wq, q, BATCH * LQQ, DMODEL, DMODEL);
    sgemm_kernel<<<gg, 256>>>(kvln, Wk, k, BATCH * LKK, DMODEL, DMODEL);
    sgemm_kernel<<<gg, 256>>>(kvln, Wv, v, BATCH * LKK, DMODEL, DMODEL);

    int nvec = BATCH * LQQ * NHEAD; // 131072 head vectors
    l2norm_kernel<<<(nvec * 32) / 256, 256>>>(q, nvec);
    l2norm_kernel<<<(nvec * 32) / 256, 256>>>(k, nvec);

    attn_kernel<<<dim3(LQQ / 64, NHEAD, BATCH), 256, smem_attn>>>(q, k, v, mask, taup, ao);

    sgemm_kernel<<<gg, 256>>>(ao, Wo, out, BATCH * LQQ, DMODEL, DMODEL);
}

// round 2
// speedup vs baseline: 2.5952x; 2.5952x over previous
#include <cuda_runtime.h>
#include <math.h>

// Problem constants
#define BATCH 4
#define LQQ   2048
#define LKK   2048
#define DMODEL 1024
#define NHEAD 16
#define DHEAD 64

// Scratch (static device arrays -- no runtime allocation allowed)
__device__ float g_qln [BATCH * LQQ * DMODEL];
__device__ float g_kvln[BATCH * LKK * DMODEL];
__device__ float g_q   [BATCH * LQQ * DMODEL];
__device__ float g_k   [BATCH * LKK * DMODEL];
__device__ float g_v   [BATCH * LKK * DMODEL];
__device__ float g_ao  [BATCH * LQQ * DMODEL];
__device__ int   g_mask_mode; // 0=uint8, 1=int32, 2=float32

// ---------------------------------------------------------------------------
// tf32 helpers
// ---------------------------------------------------------------------------
__device__ __forceinline__ unsigned f2tf(float f) {
    unsigned u;
    asm("cvt.rna.tf32.f32 %0, %1;" : "=r"(u) : "f"(f));
    return u;
}

__device__ __forceinline__ void mma_tf32(float c[4],
                                         unsigned a0, unsigned a1, unsigned a2, unsigned a3,
                                         unsigned b0, unsigned b1) {
    asm volatile(
        "mma.sync.aligned.m16n8k8.row.col.f32.tf32.tf32.f32 "
        "{%0,%1,%2,%3},{%4,%5,%6,%7},{%8,%9},{%0,%1,%2,%3};"
        : "+f"(c[0]), "+f"(c[1]), "+f"(c[2]), "+f"(c[3])
        : "r"(a0), "r"(a1), "r"(a2), "r"(a3), "r"(b0), "r"(b1));
}

// ---------------------------------------------------------------------------
// Mask dtype detection (bool array may arrive as u8/i32/f32)
// ---------------------------------------------------------------------------
__global__ void detect_mask_kernel(const unsigned char* __restrict__ m) {
    __shared__ int nz[4];
    if (threadIdx.x < 4) nz[threadIdx.x] = 0;
    __syncthreads();
    int loc = 0;
    for (int i = threadIdx.x; i < 8192; i += blockDim.x)
        if (m[i]) loc = 1;
    if (loc) atomicOr(&nz[threadIdx.x & 3], 1);
    __syncthreads();
    if (threadIdx.x == 0) {
        int mode;
        int tot = nz[0] | nz[1] | nz[2] | nz[3];
        if (!tot)                          mode = 0;
        else if (!(nz[1] | nz[2] | nz[3])) mode = 1; // int32 LE
        else if (!(nz[0] | nz[1]))         mode = 2; // float32 (0x3F800000)
        else                               mode = 0; // uint8/bool
        g_mask_mode = mode;
    }
}

// ---------------------------------------------------------------------------
// LayerNorm: one block per row of 1024, 256 threads, float4 paths.
// ---------------------------------------------------------------------------
__global__ void ln_kernel(const float* __restrict__ x,
                          const float* __restrict__ w,
                          const float* __restrict__ bia,
                          float* __restrict__ out) {
    int row = blockIdx.x;
    int tid = threadIdx.x;
    const float4* xr = reinterpret_cast<const float4*>(x + (size_t)row * DMODEL);
    float4 a = xr[tid];
    float s  = a.x + a.y + a.z + a.w;
    float ss = a.x * a.x + a.y * a.y + a.z * a.z + a.w * a.w;

    __shared__ float rs[8], rss[8], stats[2];
    #pragma unroll
    for (int o = 16; o; o >>= 1) {
        s  += __shfl_xor_sync(0xffffffffu, s,  o);
        ss += __shfl_xor_sync(0xffffffffu, ss, o);
    }
    int wid = tid >> 5, lane = tid & 31;
    if (!lane) { rs[wid] = s; rss[wid] = ss; }
    __syncthreads();
    if (tid == 0) {
        float S = 0.f, SS = 0.f;
        #pragma unroll
        for (int i = 0; i < 8; i++) { S += rs[i]; SS += rss[i]; }
        float mean = S * (1.0f / DMODEL);
        float var  = SS * (1.0f / DMODEL) - mean * mean;
        stats[0] = mean;
        stats[1] = rsqrtf(var + 1e-5f);
    }
    __syncthreads();
    float mean = stats[0], rstd = stats[1];
    float4 wv = reinterpret_cast<const float4*>(w)[tid];
    float4 bv = reinterpret_cast<const float4*>(bia)[tid];
    float4 o;
    o.x = (a.x - mean) * rstd * wv.x + bv.x;
    o.y = (a.y - mean) * rstd * wv.y + bv.y;
    o.z = (a.z - mean) * rstd * wv.z + bv.z;
    o.w = (a.w - mean) * rstd * wv.w + bv.w;
    reinterpret_cast<float4*>(out + (size_t)row * DMODEL)[tid] = o;
}

// ---------------------------------------------------------------------------
// tf32 tensor-core GEMM: C[M,N] = A[M,K] @ B[K,N], row-major.
// 128x128x16 tiles, 256 threads (8 warps in 2x4), warp tile 64x32,
// mma.m16n8k8.tf32, conflict-free padded smem.
// ---------------------------------------------------------------------------
#define TBM 128
#define TBN 128
#define TBK 16
#define APAD 20   // stride for As[128][20]  (20m+k mod 32 collision-free)
#define BPAD 136  // stride for Bs[16][136]  (8k+n  mod 32 collision-free)

__global__ void tgemm_kernel(const float* __restrict__ A,
                             const float* __restrict__ Bm,
                             float* __restrict__ C,
                             int M, int N, int K) {
    __shared__ unsigned As[TBM * APAD];
    __shared__ unsigned Bs[TBK * BPAD];

    int tid = threadIdx.x;
    int wid = tid >> 5, lane = tid & 31;
    int wm = wid >> 2, wn = wid & 3;                // 2 x 4 warp grid
    int m0 = blockIdx.y * TBM, n0 = blockIdx.x * TBN;

    float acc[4][4][4];
    #pragma unroll
    for (int i = 0; i < 4; i++)
        #pragma unroll
        for (int j = 0; j < 4; j++)
            #pragma unroll
            for (int t = 0; t < 4; t++) acc[i][j][t] = 0.f;

    int ar = tid >> 2;             // 0..63 (+64)
    int ak = (tid & 3) << 2;       // 0,4,8,12
    int br = tid >> 5;             // 0..7 (+8)
    int bc = (tid & 31) << 2;      // 0..124

    const float* Ag = A + (size_t)(m0 + ar) * K + ak;
    const float* Bg = Bm + (size_t)br * N + n0 + bc;

    int arow = wm * 64 + (lane >> 2);
    int acol = lane & 3;
    int bn   = wn * 32 + (lane >> 2);

    for (int k0 = 0; k0 < K; k0 += TBK) {
        float4 a0v = *(const float4*)(Ag + k0);
        float4 a1v = *(const float4*)(Ag + (size_t)64 * K + k0);
        float4 b0v = *(const float4*)(Bg + (size_t)k0 * N);
        float4 b1v = *(const float4*)(Bg + (size_t)(k0 + 8) * N);
        __syncthreads();
        uint4 ua0 = make_uint4(f2tf(a0v.x), f2tf(a0v.y), f2tf(a0v.z), f2tf(a0v.w));
        uint4 ua1 = make_uint4(f2tf(a1v.x), f2tf(a1v.y), f2tf(a1v.z), f2tf(a1v.w));
        uint4 ub0 = make_uint4(f2tf(b0v.x), f2tf(b0v.y), f2tf(b0v.z), f2tf(b0v.w));
        uint4 ub1 = make_uint4(f2tf(b1v.x), f2tf(b1v.y), f2tf(b1v.z), f2tf(b1v.w));
        *(uint4*)&As[ar * APAD + ak]        = ua0;
        *(uint4*)&As[(ar + 64) * APAD + ak] = ua1;
        *(uint4*)&Bs[br * BPAD + bc]        = ub0;
        *(uint4*)&Bs[(br + 8) * BPAD + bc]  = ub1;
        __syncthreads();

        #pragma unroll
        for (int ks = 0; ks < 2; ks++) {
            int kb = ks * 8;
            unsigned af[4][4];
            #pragma unroll
            for (int mf = 0; mf < 4; mf++) {
                int r = arow + mf * 16;
                af[mf][0] = As[r * APAD + kb + acol];
                af[mf][1] = As[(r + 8) * APAD + kb + acol];
                af[mf][2] = As[r * APAD + kb + acol + 4];
                af[mf][3] = As[(r + 8) * APAD + kb + acol + 4];
            }
            unsigned bf[4][2];
            #pragma unroll
            for (int nf = 0; nf < 4; nf++) {
                bf[nf][0] = Bs[(kb + acol) * BPAD + bn + nf * 8];
                bf[nf][1] = Bs[(kb + 4 + acol) * BPAD + bn + nf * 8];
            }
            #pragma unroll
            for (int mf = 0; mf < 4; mf++)
                #pragma unroll
                for (int nf = 0; nf < 4; nf++)
                    mma_tf32(acc[mf][nf], af[mf][0], af[mf][1], af[mf][2], af[mf][3],
                             bf[nf][0], bf[nf][1]);
        }
    }

    int crow = m0 + wm * 64 + (lane >> 2);
    int ccol = n0 + wn * 32 + (lane & 3) * 2;
    #pragma unroll
    for (int mf = 0; mf < 4; mf++) {
        #pragma unroll
        for (int nf = 0; nf < 4; nf++) {
            int r = crow + mf * 16;
            int c = ccol + nf * 8;
            *(float2*)&C[(size_t)r * N + c]       = make_float2(acc[mf][nf][0], acc[mf][nf][1]);
            *(float2*)&C[(size_t)(r + 8) * N + c] = make_float2(acc[mf][nf][2], acc[mf][nf][3]);
        }
    }
}

// ---------------------------------------------------------------------------
// L2 norm over contiguous 64-float head vectors: one warp per vector.
// ---------------------------------------------------------------------------
__global__ void l2norm_kernel(float* __restrict__ d, int nvec) {
    int idx  = blockIdx.x * blockDim.x + threadIdx.x;
    int warp = idx >> 5;
    int lane = idx & 31;
    if (warp >= nvec) return;
    float2* p = reinterpret_cast<float2*>(d) + (size_t)warp * 32 + lane;
    float2 v = *p;
    float ss = v.x * v.x + v.y * v.y;
    #pragma unroll
    for (int o = 16; o; o >>= 1) ss += __shfl_xor_sync(0xffffffffu, ss, o);
    float sc = 1.0f / fmaxf(sqrtf(ss), 1e-12f);
    v.x *= sc; v.y *= sc;
    *p = v;
}

// ---------------------------------------------------------------------------
// Flash attention with tf32 tensor cores.
// Grid (LQ/64, H, B), 256 threads (8 warps).
// S = Q.K^T via mma (warp grid 4m x 2n), parallel softmax (64 rows x 4 lanes),
// O += P.V via mma with online-softmax rescale.
// ---------------------------------------------------------------------------
#define QPAD 68   // 4r+k mod 32 collision-free
#define VPAD 72   // 8k+d mod 32 collision-free

__global__ void attn_kernel(const float* __restrict__ Q,
                            const float* __restrict__ Kp,
                            const float* __restrict__ V,
                            const void*  __restrict__ mask,
                            const float* __restrict__ tau_p,
                            float* __restrict__ O) {
    extern __shared__ unsigned char smraw[];
    unsigned* Qs = (unsigned*)smraw;                   // 64*68 tf32
    unsigned* Ks = Qs + 64 * QPAD;                     // 64*68 tf32
    unsigned* Vs = Ks + 64 * QPAD;                     // 64*72 tf32
    float*    Sb = (float*)(Vs + 64 * VPAD);           // 64*68 f32
    float*    mrow  = Sb + 64 * QPAD;                  // 64
    float*    lrow  = mrow + 64;
    float*    corr  = lrow + 64;
    float*    maskS = corr + 64;

    int tid  = threadIdx.x;
    int wid  = tid >> 5, lane = tid & 31;
    int wm   = wid >> 1;          // 0..3 : 16-row slab
    int wn   = wid & 1;           // 0..1 : 32-col slab
    int q0   = blockIdx.x * 64;
    int h    = blockIdx.y;
    int b    = blockIdx.z;

    float inv_tau = 1.0f / (*tau_p + 1e-6f);
    int mode = g_mask_mode;
    const unsigned char* m8  = (const unsigned char*)mask;
    const int*           m32 = (const int*)mask;
    const float*         mf  = (const float*)mask;

    // Load Q tile (convert to tf32)
    #pragma unroll
    for (int i = 0; i < 4; i++) {
        int fid = tid + i * 256;          // 0..1023 float4 slots
        int r = fid >> 4, c4 = (fid & 15) << 2;
        float4 qv = *(const float4*)&Q[((size_t)(b * LQQ + q0 + r)) * DMODEL + h * DHEAD + c4];
        *(uint4*)&Qs[r * QPAD + c4] = make_uint4(f2tf(qv.x), f2tf(qv.y), f2tf(qv.z), f2tf(qv.w));
    }
    if (tid < 64) { mrow[tid] = -1e30f; lrow[tid] = 0.f; }

    float oacc[4][4];
    #pragma unroll
    for (int i = 0; i < 4; i++)
        #pragma unroll
        for (int j = 0; j < 4; j++) oacc[i][j] = 0.f;

    int rA   = wm * 16 + (lane >> 2);   // A-frag row
    int kA   = lane & 3;                // A-frag k
    int nB   = wn * 32 + (lane >> 2);   // B-frag n

    for (int kt = 0; kt < LKK / 64; kt++) {
        int k0 = kt * 64;
        __syncthreads();
        // Load K, V tiles (convert to tf32) + mask row
        #pragma unroll
        for (int i = 0; i < 4; i++) {
            int fid = tid + i * 256;
            int r = fid >> 4, c4 = (fid & 15) << 2;
            size_t g = ((size_t)(b * LKK + k0 + r)) * DMODEL + h * DHEAD + c4;
            float4 kv = *(const float4*)&Kp[g];
            float4 vv = *(const float4*)&V[g];
            *(uint4*)&Ks[r * QPAD + c4] = make_uint4(f2tf(kv.x), f2tf(kv.y), f2tf(kv.z), f2tf(kv.w));
            *(uint4*)&Vs[r * VPAD + c4] = make_uint4(f2tf(vv.x), f2tf(vv.y), f2tf(vv.z), f2tf(vv.w));
        }
        if (tid < 64) {
            int km = b * LKK + k0 + tid;
            bool mm = (mode == 0) ? (m8[km] != 0)
                    : (mode == 1) ? (m32[km] != 0)
                                  : (mf[km] != 0.f);
            maskS[tid] = mm ? 1.f : 0.f;
        }
        __syncthreads();

        // S = Q . K^T  (per warp: 16 rows x 32 cols)
        float sacc[4][4];
        #pragma unroll
        for (int i = 0; i < 4; i++)
            #pragma unroll
            for (int j = 0; j < 4; j++) sacc[i][j] = 0.f;

        #pragma unroll
        for (int ks = 0; ks < 8; ks++) {
            int kb = ks * 8;
            unsigned a0 = Qs[rA * QPAD + kb + kA];
            unsigned a1 = Qs[(rA + 8) * QPAD + kb + kA];
            unsigned a2 = Qs[rA * QPAD + kb + kA + 4];
            unsigned a3 = Qs[(rA + 8) * QPAD + kb + kA + 4];
            #pragma unroll
            for (int nf = 0; nf < 4; nf++) {
                unsigned b0 = Ks[(nB + nf * 8) * QPAD + kb + kA];
                unsigned b1 = Ks[(nB + nf * 8) * QPAD + kb + kA + 4];
                mma_tf32(sacc[nf], a0, a1, a2, a3, b0, b1);
            }
        }
        // write S frags to smem
        {
            int sr = wm * 16 + (lane >> 2);
            int sc = wn * 32 + (lane & 3) * 2;
            #pragma unroll
            for (int nf = 0; nf < 4; nf++) {
                *(float2*)&Sb[sr * QPAD + sc + nf * 8]       = make_float2(sacc[nf][0], sacc[nf][1]);
                *(float2*)&Sb[(sr + 8) * QPAD + sc + nf * 8] = make_float2(sacc[nf][2], sacc[nf][3]);
            }
        }
        __syncthreads();

        // Parallel softmax: 64 rows x 4 lanes, 16 cols each
        {
            int row  = tid >> 2;
            int part = tid & 3;
            float* srow = Sb + row * QPAD + part * 16;
            const float4* mrow4 = (const float4*)(maskS + part * 16);
            float4 vv[4];
            float mx = -1e30f;
            #pragma unroll
            for (int j = 0; j < 4; j++) {
                float4 sv = *(float4*)(srow + j * 4);
                float4 mk = mrow4[j];
                vv[j].x = (mk.x != 0.f) ? -1e30f : sv.x * inv_tau;
                vv[j].y = (mk.y != 0.f) ? -1e30f : sv.y * inv_tau;
                vv[j].z = (mk.z != 0.f) ? -1e30f : sv.z * inv_tau;
                vv[j].w = (mk.w != 0.f) ? -1e30f : sv.w * inv_tau;
                mx = fmaxf(mx, fmaxf(fmaxf(vv[j].x, vv[j].y), fmaxf(vv[j].z, vv[j].w)));
            }
            mx = fmaxf(mx, __shfl_xor_sync(0xffffffffu, mx, 1));
            mx = fmaxf(mx, __shfl_xor_sync(0xffffffffu, mx, 2));
            float mold = mrow[row];
            mx = fmaxf(mx, mold);
            float sum = 0.f;
            #pragma unroll
            for (int j = 0; j < 4; j++) {
                float4 e;
                e.x = __expf(vv[j].x - mx);
                e.y = __expf(vv[j].y - mx);
                e.z = __expf(vv[j].z - mx);
                e.w = __expf(vv[j].w - mx);
                sum += e.x + e.y + e.z + e.w;
                *(float4*)(srow + j * 4) = e;
            }
            sum += __shfl_xor_sync(0xffffffffu, sum, 1);
            sum += __shfl_xor_sync(0xffffffffu, sum, 2);
            if (part == 0) {
                float cr = __expf(mold - mx);
                corr[row] = cr;
                lrow[row] = lrow[row] * cr + sum;
                mrow[row] = mx;
            }
        }
        __syncthreads();

        // Rescale accumulators, then O += P . V
        {
            int r0 = wm * 16 + (lane >> 2);
            float cr0 = corr[r0];
            float cr1 = corr[r0 + 8];
            #pragma unroll
            for (int nf = 0; nf < 4; nf++) {
                oacc[nf][0] *= cr0; oacc[nf][1] *= cr0;
                oacc[nf][2] *= cr1; oacc[nf][3] *= cr1;
            }
        }
        #pragma unroll
        for (int ks = 0; ks < 8; ks++) {
            int kb = ks * 8;
            unsigned a0 = f2tf(Sb[rA * QPAD + kb + kA]);
            unsigned a1 = f2tf(Sb[(rA + 8) * QPAD + kb + kA]);
            unsigned a2 = f2tf(Sb[rA * QPAD + kb + kA + 4]);
            unsigned a3 = f2tf(Sb[(rA + 8) * QPAD + kb + kA + 4]);
            #pragma unroll
            for (int nf = 0; nf < 4; nf++) {
                unsigned b0 = Vs[(kb + kA) * VPAD + nB + nf * 8];
                unsigned b1 = Vs[(kb + kA + 4) * VPAD + nB + nf * 8];
                mma_tf32(oacc[nf], a0, a1, a2, a3, b0, b1);
            }
        }
    }
    __syncthreads();

    // Epilogue: divide by l, store
    {
        int r0 = wm * 16 + (lane >> 2);
        float li0 = 1.0f / lrow[r0];
        float li1 = 1.0f / lrow[r0 + 8];
        int gcol = h * DHEAD + wn * 32 + (lane & 3) * 2;
        #pragma unroll
        for (int nf = 0; nf < 4; nf++) {
            size_t base0 = ((size_t)(b * LQQ + q0 + r0)) * DMODEL + gcol + nf * 8;
            size_t base1 = ((size_t)(b * LQQ + q0 + r0 + 8)) * DMODEL + gcol + nf * 8;
            *(float2*)&O[base0] = make_float2(oacc[nf][0] * li0, oacc[nf][1] * li0);
            *(float2*)&O[base1] = make_float2(oacc[nf][2] * li1, oacc[nf][3] * li1);
        }
    }
}

// ---------------------------------------------------------------------------
// Launcher
// ---------------------------------------------------------------------------
extern "C" void kernel_launch(void* const* d_in, const int* in_sizes, int n_in,
                              void* d_out, int out_size) {
    const float* x     = (const float*)d_in[0];
    const float* ctx   = (const float*)d_in[1];
    const void*  mask  = d_in[2];
    const float* lnqw  = (const float*)d_in[3];
    const float* lnqb  = (const float*)d_in[4];
    const float* lncw  = (const float*)d_in[5];
    const float* lncb  = (const float*)d_in[6];
    const float* Wq    = (const float*)d_in[7];
    const float* Wk    = (const float*)d_in[8];
    const float* Wv    = (const float*)d_in[9];
    const float* Wo    = (const float*)d_in[10];
    const float* taup  = (const float*)d_in[11];
    float* out = (float*)d_out;

    float *qln, *kvln, *q, *k, *v, *ao;
    cudaGetSymbolAddress((void**)&qln,  g_qln);
    cudaGetSymbolAddress((void**)&kvln, g_kvln);
    cudaGetSymbolAddress((void**)&q,    g_q);
    cudaGetSymbolAddress((void**)&k,    g_k);
    cudaGetSymbolAddress((void**)&v,    g_v);
    cudaGetSymbolAddress((void**)&ao,   g_ao);

    // attention dynamic smem
    const int smem_attn = (int)((64 * QPAD * 2 + 64 * VPAD) * sizeof(unsigned)
                              + (64 * QPAD + 4 * 64) * sizeof(float));
    cudaFuncSetAttribute(attn_kernel, cudaFuncAttributeMaxDynamicSharedMemorySize, smem_attn);

    detect_mask_kernel<<<1, 256>>>((const unsigned char*)mask);

    ln_kernel<<<BATCH * LQQ, 256>>>(x,   lnqw, lnqb, qln);
    ln_kernel<<<BATCH * LKK, 256>>>(ctx, lncw, lncb, kvln);

    dim3 gg(DMODEL / TBN, (BATCH * LQQ) / TBM);
    tgemm_kernel<<<gg, 256>>>(qln,  Wq, q, BATCH * LQQ, DMODEL, DMODEL);
    tgemm_kernel<<<gg, 256>>>(kvln, Wk, k, BATCH * LKK, DMODEL, DMODEL);
    tgemm_kernel<<<gg, 256>>>(kvln, Wv, v, BATCH * LKK, DMODEL, DMODEL);

    int nvec = BATCH * LQQ * NHEAD;
    l2norm_kernel<<<(nvec * 32) / 256, 256>>>(q, nvec);
    l2norm_kernel<<<(nvec * 32) / 256, 256>>>(k, nvec);

    attn_kernel<<<dim3(LQQ / 64, NHEAD, BATCH), 256, smem_attn>>>(q, k, v, mask, taup, ao);

    tgemm_kernel<<<gg, 256>>>(ao, Wo, out, BATCH * LQQ, DMODEL, DMODEL);
}

// round 3
// speedup vs baseline: 3.0587x; 1.1786x over previous
#include <cuda_runtime.h>
#include <math.h>

// Problem constants
#define BATCH 4
#define LQQ   2048
#define LKK   2048
#define DMODEL 1024
#define NHEAD 16
#define DHEAD 64

// Scratch (static device arrays -- no runtime allocation allowed)
__device__ float g_qln [BATCH * LQQ * DMODEL];
__device__ float g_kvln[BATCH * LKK * DMODEL];
__device__ float g_q   [BATCH * LQQ * DMODEL];
__device__ float g_k   [BATCH * LKK * DMODEL];
__device__ float g_v   [BATCH * LKK * DMODEL];
__device__ float g_ao  [BATCH * LQQ * DMODEL];
__device__ float g_maskf[BATCH * LKK];   // 0.0 = masked, 1.0 = keep
__device__ int   g_mask_mode;            // 0=uint8, 1=int32, 2=float32

// ---------------------------------------------------------------------------
// tf32 / cp.async helpers
// ---------------------------------------------------------------------------
__device__ __forceinline__ unsigned f2tf(float f) {
    unsigned u;
    asm("cvt.rna.tf32.f32 %0, %1;" : "=r"(u) : "f"(f));
    return u;
}

__device__ __forceinline__ void mma_tf32(float c[4],
                                         unsigned a0, unsigned a1, unsigned a2, unsigned a3,
                                         unsigned b0, unsigned b1) {
    asm volatile(
        "mma.sync.aligned.m16n8k8.row.col.f32.tf32.tf32.f32 "
        "{%0,%1,%2,%3},{%4,%5,%6,%7},{%8,%9},{%0,%1,%2,%3};"
        : "+f"(c[0]), "+f"(c[1]), "+f"(c[2]), "+f"(c[3])
        : "r"(a0), "r"(a1), "r"(a2), "r"(a3), "r"(b0), "r"(b1));
}

__device__ __forceinline__ void cp_async16(void* smem_dst, const void* gmem_src) {
    unsigned sa = (unsigned)__cvta_generic_to_shared(smem_dst);
    asm volatile("cp.async.cg.shared.global [%0], [%1], 16;" :: "r"(sa), "l"(gmem_src));
}
__device__ __forceinline__ void cp_commit() {
    asm volatile("cp.async.commit_group;");
}
template <int N>
__device__ __forceinline__ void cp_wait() {
    asm volatile("cp.async.wait_group %0;" :: "n"(N));
}

// ---------------------------------------------------------------------------
// Mask dtype detection (bool array may arrive as u8/i32/f32)
// ---------------------------------------------------------------------------
__global__ void detect_mask_kernel(const unsigned char* __restrict__ m) {
    __shared__ int nz[4];
    if (threadIdx.x < 4) nz[threadIdx.x] = 0;
    __syncthreads();
    int loc = 0;
    for (int i = threadIdx.x; i < 8192; i += blockDim.x)
        if (m[i]) loc = 1;
    if (loc) atomicOr(&nz[threadIdx.x & 3], 1);
    __syncthreads();
    if (threadIdx.x == 0) {
        int mode;
        int tot = nz[0] | nz[1] | nz[2] | nz[3];
        if (!tot)                          mode = 0;
        else if (!(nz[1] | nz[2] | nz[3])) mode = 1; // int32 LE
        else if (!(nz[0] | nz[1]))         mode = 2; // float32 (0x3F800000)
        else                               mode = 0; // uint8/bool
        g_mask_mode = mode;
    }
}

// Convert mask (any dtype) into multiplicative float mask: 0 = masked, 1 = keep
__global__ void maskf_kernel(const void* __restrict__ m) {
    int i = blockIdx.x * blockDim.x + threadIdx.x;
    if (i >= BATCH * LKK) return;
    int mode = g_mask_mode;
    bool mm = (mode == 0) ? (((const unsigned char*)m)[i] != 0)
            : (mode == 1) ? (((const int*)m)[i] != 0)
                          : (((const float*)m)[i] != 0.f);
    g_maskf[i] = mm ? 0.f : 1.f;
}

// ---------------------------------------------------------------------------
// LayerNorm: one block per row of 1024, 256 threads, float4 paths.
// ---------------------------------------------------------------------------
__global__ void ln_kernel(const float* __restrict__ x,
                          const float* __restrict__ w,
                          const float* __restrict__ bia,
                          float* __restrict__ out) {
    int row = blockIdx.x;
    int tid = threadIdx.x;
    const float4* xr = reinterpret_cast<const float4*>(x + (size_t)row * DMODEL);
    float4 a = xr[tid];
    float s  = a.x + a.y + a.z + a.w;
    float ss = a.x * a.x + a.y * a.y + a.z * a.z + a.w * a.w;

    __shared__ float rs[8], rss[8], stats[2];
    #pragma unroll
    for (int o = 16; o; o >>= 1) {
        s  += __shfl_xor_sync(0xffffffffu, s,  o);
        ss += __shfl_xor_sync(0xffffffffu, ss, o);
    }
    int wid = tid >> 5, lane = tid & 31;
    if (!lane) { rs[wid] = s; rss[wid] = ss; }
    __syncthreads();
    if (tid == 0) {
        float S = 0.f, SS = 0.f;
        #pragma unroll
        for (int i = 0; i < 8; i++) { S += rs[i]; SS += rss[i]; }
        float mean = S * (1.0f / DMODEL);
        float var  = SS * (1.0f / DMODEL) - mean * mean;
        stats[0] = mean;
        stats[1] = rsqrtf(var + 1e-5f);
    }
    __syncthreads();
    float mean = stats[0], rstd = stats[1];
    float4 wv = reinterpret_cast<const float4*>(w)[tid];
    float4 bv = reinterpret_cast<const float4*>(bia)[tid];
    float4 o;
    o.x = (a.x - mean) * rstd * wv.x + bv.x;
    o.y = (a.y - mean) * rstd * wv.y + bv.y;
    o.z = (a.z - mean) * rstd * wv.z + bv.z;
    o.w = (a.w - mean) * rstd * wv.w + bv.w;
    reinterpret_cast<float4*>(out + (size_t)row * DMODEL)[tid] = o;
}

// ---------------------------------------------------------------------------
// tf32 tensor-core GEMM with cp.async 2-stage pipeline.
// C[M,N] = A[M,K] @ B[K,N], row-major. 128x128x16 tiles, 256 threads.
// One __syncthreads per K-tile; tf32 conversion at fragment load.
// ---------------------------------------------------------------------------
#define TBM 128
#define TBN 128
#define TBK 16
#define APAD 20
#define BPAD 136

__global__ void tgemm_kernel(const float* __restrict__ A,
                             const float* __restrict__ Bm,
                             float* __restrict__ C,
                             int M, int N, int K) {
    __shared__ float As[2][TBM * APAD];
    __shared__ float Bs[2][TBK * BPAD];

    int tid = threadIdx.x;
    int wid = tid >> 5, lane = tid & 31;
    int wm = wid >> 2, wn = wid & 3;                // 2 x 4 warp grid
    int m0 = blockIdx.y * TBM, n0 = blockIdx.x * TBN;

    float acc[4][4][4];
    #pragma unroll
    for (int i = 0; i < 4; i++)
        #pragma unroll
        for (int j = 0; j < 4; j++)
            #pragma unroll
            for (int t = 0; t < 4; t++) acc[i][j][t] = 0.f;

    int ar = tid >> 2;             // 0..63 (+64)
    int ak = (tid & 3) << 2;       // 0,4,8,12
    int br = tid >> 5;             // 0..7 (+8)
    int bc = (tid & 31) << 2;      // 0..124

    const float* Ag = A + (size_t)(m0 + ar) * K + ak;
    const float* Bg = Bm + (size_t)br * N + n0 + bc;

    int arow = wm * 64 + (lane >> 2);
    int acol = lane & 3;
    int bn   = wn * 32 + (lane >> 2);

    // prologue: prefetch tile 0
    {
        cp_async16(&As[0][ar * APAD + ak],        Ag);
        cp_async16(&As[0][(ar + 64) * APAD + ak], Ag + (size_t)64 * K);
        cp_async16(&Bs[0][br * BPAD + bc],        Bg);
        cp_async16(&Bs[0][(br + 8) * BPAD + bc],  Bg + (size_t)8 * N);
        cp_commit();
    }

    int nt = K / TBK;
    for (int kt = 0; kt < nt; kt++) {
        int cur = kt & 1;
        cp_wait<0>();
        __syncthreads();
        if (kt + 1 < nt) {
            int k0 = (kt + 1) * TBK;
            int nxt = cur ^ 1;
            cp_async16(&As[nxt][ar * APAD + ak],        Ag + k0);
            cp_async16(&As[nxt][(ar + 64) * APAD + ak], Ag + (size_t)64 * K + k0);
            cp_async16(&Bs[nxt][br * BPAD + bc],        Bg + (size_t)k0 * N);
            cp_async16(&Bs[nxt][(br + 8) * BPAD + bc],  Bg + (size_t)(k0 + 8) * N);
            cp_commit();
        }
        const float* Asb = As[cur];
        const float* Bsb = Bs[cur];
        #pragma unroll
        for (int ks = 0; ks < 2; ks++) {
            int kb = ks * 8;
            unsigned af[4][4];
            #pragma unroll
            for (int mf = 0; mf < 4; mf++) {
                int r = arow + mf * 16;
                af[mf][0] = f2tf(Asb[r * APAD + kb + acol]);
                af[mf][1] = f2tf(Asb[(r + 8) * APAD + kb + acol]);
                af[mf][2] = f2tf(Asb[r * APAD + kb + acol + 4]);
                af[mf][3] = f2tf(Asb[(r + 8) * APAD + kb + acol + 4]);
            }
            unsigned bf[4][2];
            #pragma unroll
            for (int nf = 0; nf < 4; nf++) {
                bf[nf][0] = f2tf(Bsb[(kb + acol) * BPAD + bn + nf * 8]);
                bf[nf][1] = f2tf(Bsb[(kb + 4 + acol) * BPAD + bn + nf * 8]);
            }
            #pragma unroll
            for (int mf = 0; mf < 4; mf++)
                #pragma unroll
                for (int nf = 0; nf < 4; nf++)
                    mma_tf32(acc[mf][nf], af[mf][0], af[mf][1], af[mf][2], af[mf][3],
                             bf[nf][0], bf[nf][1]);
        }
    }

    int crow = m0 + wm * 64 + (lane >> 2);
    int ccol = n0 + wn * 32 + (lane & 3) * 2;
    #pragma unroll
    for (int mf = 0; mf < 4; mf++) {
        #pragma unroll
        for (int nf = 0; nf < 4; nf++) {
            int r = crow + mf * 16;
            int c = ccol + nf * 8;
            *(float2*)&C[(size_t)r * N + c]       = make_float2(acc[mf][nf][0], acc[mf][nf][1]);
            *(float2*)&C[(size_t)(r + 8) * N + c] = make_float2(acc[mf][nf][2], acc[mf][nf][3]);
        }
    }
}

// ---------------------------------------------------------------------------
// L2 norm over contiguous 64-float head vectors: one warp per vector.
// ---------------------------------------------------------------------------
__global__ void l2norm_kernel(float* __restrict__ d, int nvec) {
    int idx  = blockIdx.x * blockDim.x + threadIdx.x;
    int warp = idx >> 5;
    int lane = idx & 31;
    if (warp >= nvec) return;
    float2* p = reinterpret_cast<float2*>(d) + (size_t)warp * 32 + lane;
    float2 v = *p;
    float ss = v.x * v.x + v.y * v.y;
    #pragma unroll
    for (int o = 16; o; o >>= 1) ss += __shfl_xor_sync(0xffffffffu, ss, o);
    float sc = 1.0f / fmaxf(sqrtf(ss), 1e-12f);
    v.x *= sc; v.y *= sc;
    *p = v;
}

// ---------------------------------------------------------------------------
// Flash attention, tf32 mma, FIXED-max softmax.
// q,k are unit vectors so |score| <= 1/tau: use M = |1/tau| as static max.
// No online rescale; exp applied to S fragments in registers; row sums
// accumulated in registers across all KV tiles. cp.async double-buffered K/V.
// Grid (LQ/64, H, B), 256 threads (8 warps: 4 row-slabs x 2 col-halves).
// ---------------------------------------------------------------------------
#define QPAD 68   // tf32 Q / P stride
#define VPAD 72   // f32 V stride (k-major)

__global__ void attn_kernel(const float* __restrict__ Q,
                            const float* __restrict__ Kp,
                            const float* __restrict__ V,
                            const float* __restrict__ maskf,
                            const float* __restrict__ tau_p,
                            float* __restrict__ O) {
    extern __shared__ unsigned char smraw[];
    unsigned* Qs  = (unsigned*)smraw;                  // 64*QPAD tf32
    float*    Ks  = (float*)(Qs + 64 * QPAD);          // 2 * 64*QPAD f32
    float*    Vs  = Ks + 2 * 64 * QPAD;                // 2 * 64*VPAD f32
    unsigned* Pb  = (unsigned*)(Vs + 2 * 64 * VPAD);   // 64*QPAD tf32
    float*    Ms  = (float*)(Pb + 64 * QPAD);          // 2 * 64
    float*    lpart = Ms + 128;                        // 2 * 64

    int tid  = threadIdx.x;
    int wid  = tid >> 5, lane = tid & 31;
    int wm   = wid >> 1;          // 0..3 : 16-row slab
    int wn   = wid & 1;           // 0..1 : 32-col half
    int q0   = blockIdx.x * 64;
    int h    = blockIdx.y;
    int b    = blockIdx.z;

    float inv_tau = 1.0f / (*tau_p + 1e-6f);
    float MFIX = fabsf(inv_tau);   // scores bounded by |1/tau| (unit q,k)

    // Load Q tile, convert to tf32
    #pragma unroll
    for (int i = 0; i < 4; i++) {
        int fid = tid + i * 256;
        int r = fid >> 4, c4 = (fid & 15) << 2;
        float4 qv = *(const float4*)&Q[((size_t)(b * LQQ + q0 + r)) * DMODEL + h * DHEAD + c4];
        *(uint4*)&Qs[r * QPAD + c4] = make_uint4(f2tf(qv.x), f2tf(qv.y), f2tf(qv.z), f2tf(qv.w));
    }

    // cp.async KV tile loader
    int kvr  = tid >> 2;            // 0..63
    int kvc4 = (tid & 3) << 2;      // 0,4,8,12 -> 4 chunks of 16 cols? no:
    // 64 rows x 64 cols = 1024 float4 chunks; assign 4 per thread:
    // chunk id = tid + i*256 : r = id>>4, c4 = (id&15)<<2
    const float* Kbase = Kp + ((size_t)b * LKK) * DMODEL + h * DHEAD;
    const float* Vbase = V  + ((size_t)b * LKK) * DMODEL + h * DHEAD;
    const float* Mbase = maskf + (size_t)b * LKK;

    auto load_kv = [&](int k0, int buf) {
        #pragma unroll
        for (int i = 0; i < 4; i++) {
            int fid = tid + i * 256;
            int r = fid >> 4, c4 = (fid & 15) << 2;
            size_t g = (size_t)(k0 + r) * DMODEL + c4;
            cp_async16(&Ks[buf * 64 * QPAD + r * QPAD + c4], Kbase + g);
            cp_async16(&Vs[buf * 64 * VPAD + r * VPAD + c4], Vbase + g);
        }
        if (tid < 16) cp_async16(&Ms[buf * 64 + tid * 4], Mbase + k0 + tid * 4);
        cp_commit();
    };

    load_kv(0, 0);

    float oacc[4][4];
    #pragma unroll
    for (int i = 0; i < 4; i++)
        #pragma unroll
        for (int j = 0; j < 4; j++) oacc[i][j] = 0.f;
    float lsum0 = 0.f, lsum1 = 0.f;

    int rA = wm * 16 + (lane >> 2);   // A-frag row
    int kA = lane & 3;                // A-frag k
    int nB = wn * 32 + (lane >> 2);   // B-frag n
    int sr = wm * 16 + (lane >> 2);   // S output row
    int scb = wn * 32 + (lane & 3) * 2;

    const int NT = LKK / 64;
    for (int kt = 0; kt < NT; kt++) {
        int cur = kt & 1;
        cp_wait<0>();
        __syncthreads();   // KV[cur]+mask visible; prev PV (reads of buf cur^1, Pb) done
        if (kt + 1 < NT) load_kv((kt + 1) * 64, cur ^ 1);

        const float* Ksb = Ks + cur * 64 * QPAD;
        const float* Vsb = Vs + cur * 64 * VPAD;
        const float* Msb = Ms + cur * 64;

        // S = Q . K^T
        float sacc[4][4];
        #pragma unroll
        for (int i = 0; i < 4; i++)
            #pragma unroll
            for (int j = 0; j < 4; j++) sacc[i][j] = 0.f;

        #pragma unroll
        for (int ks = 0; ks < 8; ks++) {
            int kb = ks * 8;
            unsigned a0 = Qs[rA * QPAD + kb + kA];
            unsigned a1 = Qs[(rA + 8) * QPAD + kb + kA];
            unsigned a2 = Qs[rA * QPAD + kb + kA + 4];
            unsigned a3 = Qs[(rA + 8) * QPAD + kb + kA + 4];
            #pragma unroll
            for (int nf = 0; nf < 4; nf++) {
                unsigned b0 = f2tf(Ksb[(nB + nf * 8) * QPAD + kb + kA]);
                unsigned b1 = f2tf(Ksb[(nB + nf * 8) * QPAD + kb + kA + 4]);
                mma_tf32(sacc[nf], a0, a1, a2, a3, b0, b1);
            }
        }

        // exp (fixed max) + mask, accumulate row sums, write P (tf32) to smem
        #pragma unroll
        for (int nf = 0; nf < 4; nf++) {
            int c = scb + nf * 8;
            float mk0 = Msb[c], mk1 = Msb[c + 1];
            float p00 = __expf(fminf(sacc[nf][0] * inv_tau - MFIX, 0.f)) * mk0;
            float p01 = __expf(fminf(sacc[nf][1] * inv_tau - MFIX, 0.f)) * mk1;
            float p10 = __expf(fminf(sacc[nf][2] * inv_tau - MFIX, 0.f)) * mk0;
            float p11 = __expf(fminf(sacc[nf][3] * inv_tau - MFIX, 0.f)) * mk1;
            lsum0 += p00 + p01;
            lsum1 += p10 + p11;
            *(uint2*)&Pb[sr * QPAD + c]       = make_uint2(f2tf(p00), f2tf(p01));
            *(uint2*)&Pb[(sr + 8) * QPAD + c] = make_uint2(f2tf(p10), f2tf(p11));
        }
        __syncthreads();   // Pb complete before PV mma

        // O += P . V
        #pragma unroll
        for (int ks = 0; ks < 8; ks++) {
            int kb = ks * 8;
            unsigned a0 = Pb[rA * QPAD + kb + kA];
            unsigned a1 = Pb[(rA + 8) * QPAD + kb + kA];
            unsigned a2 = Pb[rA * QPAD + kb + kA + 4];
            unsigned a3 = Pb[(rA + 8) * QPAD + kb + kA + 4];
            #pragma unroll
            for (int nf = 0; nf < 4; nf++) {
                unsigned b0 = f2tf(Vsb[(kb + kA) * VPAD + nB + nf * 8]);
                unsigned b1 = f2tf(Vsb[(kb + kA + 4) * VPAD + nB + nf * 8]);
                mma_tf32(oacc[nf], a0, a1, a2, a3, b0, b1);
            }
        }
    }

    // combine row sums: quad-reduce then across the two wn halves via smem
    lsum0 += __shfl_xor_sync(0xffffffffu, lsum0, 1);
    lsum0 += __shfl_xor_sync(0xffffffffu, lsum0, 2);
    lsum1 += __shfl_xor_sync(0xffffffffu, lsum1, 1);
    lsum1 += __shfl_xor_sync(0xffffffffu, lsum1, 2);
    __syncthreads();
    if ((lane & 3) == 0) {
        lpart[wn * 64 + sr]     = lsum0;
        lpart[wn * 64 + sr + 8] = lsum1;
    }
    __syncthreads();

    // Epilogue: divide by l, store
    {
        int r0 = wm * 16 + (lane >> 2);
        float li0 = 1.0f / (lpart[r0]     + lpart[64 + r0]);
        float li1 = 1.0f / (lpart[r0 + 8] + lpart[64 + r0 + 8]);
        int gcol = h * DHEAD + wn * 32 + (lane & 3) * 2;
        #pragma unroll
        for (int nf = 0; nf < 4; nf++) {
            size_t base0 = ((size_t)(b * LQQ + q0 + r0)) * DMODEL + gcol + nf * 8;
            size_t base1 = ((size_t)(b * LQQ + q0 + r0 + 8)) * DMODEL + gcol + nf * 8;
            *(float2*)&O[base0] = make_float2(oacc[nf][0] * li0, oacc[nf][1] * li0);
            *(float2*)&O[base1] = make_float2(oacc[nf][2] * li1, oacc[nf][3] * li1);
        }
    }
}

// ---------------------------------------------------------------------------
// Launcher
// ---------------------------------------------------------------------------
extern "C" void kernel_launch(void* const* d_in, const int* in_sizes, int n_in,
                              void* d_out, int out_size) {
    const float* x     = (const float*)d_in[0];
    const float* ctx   = (const float*)d_in[1];
    const void*  mask  = d_in[2];
    const float* lnqw  = (const float*)d_in[3];
    const float* lnqb  = (const float*)d_in[4];
    const float* lncw  = (const float*)d_in[5];
    const float* lncb  = (const float*)d_in[6];
    const float* Wq    = (const float*)d_in[7];
    const float* Wk    = (const float*)d_in[8];
    const float* Wv    = (const float*)d_in[9];
    const float* Wo    = (const float*)d_in[10];
    const float* taup  = (const float*)d_in[11];
    float* out = (float*)d_out;

    float *qln, *kvln, *q, *k, *v, *ao, *maskf;
    cudaGetSymbolAddress((void**)&qln,   g_qln);
    cudaGetSymbolAddress((void**)&kvln,  g_kvln);
    cudaGetSymbolAddress((void**)&q,     g_q);
    cudaGetSymbolAddress((void**)&k,     g_k);
    cudaGetSymbolAddress((void**)&v,     g_v);
    cudaGetSymbolAddress((void**)&ao,    g_ao);
    cudaGetSymbolAddress((void**)&maskf, g_maskf);

    // attention dynamic smem: Qs + 2*Ks + 2*Vs + Pb + Ms + lpart
    const int smem_attn = (int)((64 * QPAD) * 4 +          // Qs
                                2 * (64 * QPAD) * 4 +      // Ks
                                2 * (64 * VPAD) * 4 +      // Vs
                                (64 * QPAD) * 4 +          // Pb
                                (128 + 128) * 4);          // Ms + lpart
    cudaFuncSetAttribute(attn_kernel, cudaFuncAttributeMaxDynamicSharedMemorySize, smem_attn);

    detect_mask_kernel<<<1, 256>>>((const unsigned char*)mask);
    maskf_kernel<<<(BATCH * LKK + 255) / 256, 256>>>(mask);

    ln_kernel<<<BATCH * LQQ, 256>>>(x,   lnqw, lnqb, qln);
    ln_kernel<<<BATCH * LKK, 256>>>(ctx, lncw, lncb, kvln);

    dim3 gg(DMODEL / TBN, (BATCH * LQQ) / TBM);
    tgemm_kernel<<<gg, 256>>>(qln,  Wq, q, BATCH * LQQ, DMODEL, DMODEL);
    tgemm_kernel<<<gg, 256>>>(kvln, Wk, k, BATCH * LKK, DMODEL, DMODEL);
    tgemm_kernel<<<gg, 256>>>(kvln, Wv, v, BATCH * LKK, DMODEL, DMODEL);

    int nvec = BATCH * LQQ * NHEAD;
    l2norm_kernel<<<(nvec * 32) / 256, 256>>>(q, nvec);
    l2norm_kernel<<<(nvec * 32) / 256, 256>>>(k, nvec);

    attn_kernel<<<dim3(LQQ / 64, NHEAD, BATCH), 256, smem_attn>>>(q, k, v, maskf, taup, ao);

    tgemm_kernel<<<gg, 256>>>(ao, Wo, out, BATCH * LQQ, DMODEL, DMODEL);
}

// round 4
// speedup vs baseline: 3.4777x; 1.1370x over previous
#include <cuda_runtime.h>
#include <math.h>

// Problem constants
#define BATCH 4
#define LQQ   2048
#define LKK   2048
#define DMODEL 1024
#define NHEAD 16
#define DHEAD 64

// Scratch (static device arrays -- no runtime allocation allowed)
__device__ float g_qln [BATCH * LQQ * DMODEL];
__device__ float g_kvln[BATCH * LKK * DMODEL];
__device__ float g_q   [BATCH * LQQ * DMODEL];
__device__ float g_k   [BATCH * LKK * DMODEL];
__device__ float g_v   [BATCH * LKK * DMODEL];
__device__ float g_ao  [BATCH * LQQ * DMODEL];
__device__ float g_wq  [DMODEL * DMODEL];
__device__ float g_wk  [DMODEL * DMODEL];
__device__ float g_wv  [DMODEL * DMODEL];
__device__ float g_wo  [DMODEL * DMODEL];
__device__ float g_maskf[BATCH * LKK];   // 0.0 = masked, 1.0 = keep
__device__ int   g_mask_mode;            // 0=uint8, 1=int32, 2=float32

// ---------------------------------------------------------------------------
// tf32 / cp.async helpers
// ---------------------------------------------------------------------------
__device__ __forceinline__ unsigned f2tf(float f) {
    unsigned u;
    asm("cvt.rna.tf32.f32 %0, %1;" : "=r"(u) : "f"(f));
    return u;
}
__device__ __forceinline__ float roundtf(float f) {
    return __uint_as_float(f2tf(f));
}

__device__ __forceinline__ void mma_tf32(float c[4],
                                         unsigned a0, unsigned a1, unsigned a2, unsigned a3,
                                         unsigned b0, unsigned b1) {
    asm volatile(
        "mma.sync.aligned.m16n8k8.row.col.f32.tf32.tf32.f32 "
        "{%0,%1,%2,%3},{%4,%5,%6,%7},{%8,%9},{%0,%1,%2,%3};"
        : "+f"(c[0]), "+f"(c[1]), "+f"(c[2]), "+f"(c[3])
        : "r"(a0), "r"(a1), "r"(a2), "r"(a3), "r"(b0), "r"(b1));
}

__device__ __forceinline__ void cp_async16(void* smem_dst, const void* gmem_src) {
    unsigned sa = (unsigned)__cvta_generic_to_shared(smem_dst);
    asm volatile("cp.async.cg.shared.global [%0], [%1], 16;" :: "r"(sa), "l"(gmem_src));
}
__device__ __forceinline__ void cp_commit() {
    asm volatile("cp.async.commit_group;");
}
template <int N>
__device__ __forceinline__ void cp_wait() {
    asm volatile("cp.async.wait_group %0;" :: "n"(N));
}

// ---------------------------------------------------------------------------
// Mask dtype detection (bool array may arrive as u8/i32/f32)
// ---------------------------------------------------------------------------
__global__ void detect_mask_kernel(const unsigned char* __restrict__ m) {
    __shared__ int nz[4];
    if (threadIdx.x < 4) nz[threadIdx.x] = 0;
    __syncthreads();
    int loc = 0;
    for (int i = threadIdx.x; i < 8192; i += blockDim.x)
        if (m[i]) loc = 1;
    if (loc) atomicOr(&nz[threadIdx.x & 3], 1);
    __syncthreads();
    if (threadIdx.x == 0) {
        int mode;
        int tot = nz[0] | nz[1] | nz[2] | nz[3];
        if (!tot)                          mode = 0;
        else if (!(nz[1] | nz[2] | nz[3])) mode = 1; // int32 LE
        else if (!(nz[0] | nz[1]))         mode = 2; // float32 (0x3F800000)
        else                               mode = 0; // uint8/bool
        g_mask_mode = mode;
    }
}

// Convert mask (any dtype) into multiplicative float mask: 0 = masked, 1 = keep
__global__ void maskf_kernel(const void* __restrict__ m) {
    int i = blockIdx.x * blockDim.x + threadIdx.x;
    if (i >= BATCH * LKK) return;
    int mode = g_mask_mode;
    bool mm = (mode == 0) ? (((const unsigned char*)m)[i] != 0)
            : (mode == 1) ? (((const int*)m)[i] != 0)
                          : (((const float*)m)[i] != 0.f);
    g_maskf[i] = mm ? 0.f : 1.f;
}

// Round fp32 array to tf32 (rna), float4 vectorized. n4 = count/4.
__global__ void round_tf32_kernel(const float4* __restrict__ in,
                                  float4* __restrict__ out, int n4) {
    int i = blockIdx.x * blockDim.x + threadIdx.x;
    if (i >= n4) return;
    float4 v = in[i];
    v.x = roundtf(v.x); v.y = roundtf(v.y);
    v.z = roundtf(v.z); v.w = roundtf(v.w);
    out[i] = v;
}

// ---------------------------------------------------------------------------
// LayerNorm: one block per row of 1024, 256 threads, float4 paths.
// Output is tf32-rounded (feeds tensor-core GEMMs directly).
// ---------------------------------------------------------------------------
__global__ void ln_kernel(const float* __restrict__ x,
                          const float* __restrict__ w,
                          const float* __restrict__ bia,
                          float* __restrict__ out) {
    int row = blockIdx.x;
    int tid = threadIdx.x;
    const float4* xr = reinterpret_cast<const float4*>(x + (size_t)row * DMODEL);
    float4 a = xr[tid];
    float s  = a.x + a.y + a.z + a.w;
    float ss = a.x * a.x + a.y * a.y + a.z * a.z + a.w * a.w;

    __shared__ float rs[8], rss[8], stats[2];
    #pragma unroll
    for (int o = 16; o; o >>= 1) {
        s  += __shfl_xor_sync(0xffffffffu, s,  o);
        ss += __shfl_xor_sync(0xffffffffu, ss, o);
    }
    int wid = tid >> 5, lane = tid & 31;
    if (!lane) { rs[wid] = s; rss[wid] = ss; }
    __syncthreads();
    if (tid == 0) {
        float S = 0.f, SS = 0.f;
        #pragma unroll
        for (int i = 0; i < 8; i++) { S += rs[i]; SS += rss[i]; }
        float mean = S * (1.0f / DMODEL);
        float var  = SS * (1.0f / DMODEL) - mean * mean;
        stats[0] = mean;
        stats[1] = rsqrtf(var + 1e-5f);
    }
    __syncthreads();
    float mean = stats[0], rstd = stats[1];
    float4 wv = reinterpret_cast<const float4*>(w)[tid];
    float4 bv = reinterpret_cast<const float4*>(bia)[tid];
    float4 o;
    o.x = roundtf((a.x - mean) * rstd * wv.x + bv.x);
    o.y = roundtf((a.y - mean) * rstd * wv.y + bv.y);
    o.z = roundtf((a.z - mean) * rstd * wv.z + bv.z);
    o.w = roundtf((a.w - mean) * rstd * wv.w + bv.w);
    reinterpret_cast<float4*>(out + (size_t)row * DMODEL)[tid] = o;
}

// ---------------------------------------------------------------------------
// tf32 tensor-core GEMM with cp.async 2-stage pipeline.
// Inputs are PRE-ROUNDED to tf32 -> zero cvt in the inner loop.
// C[M,N] = A[M,K] @ B[K,N], row-major. 128x128x16 tiles, 256 threads.
// roundOut: tf32-round the epilogue stores (for tensors feeding later mmas).
// ---------------------------------------------------------------------------
#define TBM 128
#define TBN 128
#define TBK 16
#define APAD 20
#define BPAD 136

__global__ void tgemm_kernel(const float* __restrict__ A,
                             const float* __restrict__ Bm,
                             float* __restrict__ C,
                             int M, int N, int K, int roundOut) {
    __shared__ float As[2][TBM * APAD];
    __shared__ float Bs[2][TBK * BPAD];

    int tid = threadIdx.x;
    int wid = tid >> 5, lane = tid & 31;
    int wm = wid >> 2, wn = wid & 3;                // 2 x 4 warp grid
    int m0 = blockIdx.y * TBM, n0 = blockIdx.x * TBN;

    float acc[4][4][4];
    #pragma unroll
    for (int i = 0; i < 4; i++)
        #pragma unroll
        for (int j = 0; j < 4; j++)
            #pragma unroll
            for (int t = 0; t < 4; t++) acc[i][j][t] = 0.f;

    int ar = tid >> 2;             // 0..63 (+64)
    int ak = (tid & 3) << 2;       // 0,4,8,12
    int br = tid >> 5;             // 0..7 (+8)
    int bc = (tid & 31) << 2;      // 0..124

    const float* Ag = A + (size_t)(m0 + ar) * K + ak;
    const float* Bg = Bm + (size_t)br * N + n0 + bc;

    int arow = wm * 64 + (lane >> 2);
    int acol = lane & 3;
    int bn   = wn * 32 + (lane >> 2);

    // prologue: prefetch tile 0
    {
        cp_async16(&As[0][ar * APAD + ak],        Ag);
        cp_async16(&As[0][(ar + 64) * APAD + ak], Ag + (size_t)64 * K);
        cp_async16(&Bs[0][br * BPAD + bc],        Bg);
        cp_async16(&Bs[0][(br + 8) * BPAD + bc],  Bg + (size_t)8 * N);
        cp_commit();
    }

    int nt = K / TBK;
    for (int kt = 0; kt < nt; kt++) {
        int cur = kt & 1;
        cp_wait<0>();
        __syncthreads();
        if (kt + 1 < nt) {
            int k0 = (kt + 1) * TBK;
            int nxt = cur ^ 1;
            cp_async16(&As[nxt][ar * APAD + ak],        Ag + k0);
            cp_async16(&As[nxt][(ar + 64) * APAD + ak], Ag + (size_t)64 * K + k0);
            cp_async16(&Bs[nxt][br * BPAD + bc],        Bg + (size_t)k0 * N);
            cp_async16(&Bs[nxt][(br + 8) * BPAD + bc],  Bg + (size_t)(k0 + 8) * N);
            cp_commit();
        }
        const unsigned* Asb = (const unsigned*)As[cur];
        const unsigned* Bsb = (const unsigned*)Bs[cur];
        #pragma unroll
        for (int ks = 0; ks < 2; ks++) {
            int kb = ks * 8;
            unsigned af[4][4];
            #pragma unroll
            for (int mf = 0; mf < 4; mf++) {
                int r = arow + mf * 16;
                af[mf][0] = Asb[r * APAD + kb + acol];
                af[mf][1] = Asb[(r + 8) * APAD + kb + acol];
                af[mf][2] = Asb[r * APAD + kb + acol + 4];
                af[mf][3] = Asb[(r + 8) * APAD + kb + acol + 4];
            }
            unsigned bf[4][2];
            #pragma unroll
            for (int nf = 0; nf < 4; nf++) {
                bf[nf][0] = Bsb[(kb + acol) * BPAD + bn + nf * 8];
                bf[nf][1] = Bsb[(kb + 4 + acol) * BPAD + bn + nf * 8];
            }
            #pragma unroll
            for (int mf = 0; mf < 4; mf++)
                #pragma unroll
                for (int nf = 0; nf < 4; nf++)
                    mma_tf32(acc[mf][nf], af[mf][0], af[mf][1], af[mf][2], af[mf][3],
                             bf[nf][0], bf[nf][1]);
        }
    }

    int crow = m0 + wm * 64 + (lane >> 2);
    int ccol = n0 + wn * 32 + (lane & 3) * 2;
    #pragma unroll
    for (int mf = 0; mf < 4; mf++) {
        #pragma unroll
        for (int nf = 0; nf < 4; nf++) {
            int r = crow + mf * 16;
            int c = ccol + nf * 8;
            float v0 = acc[mf][nf][0], v1 = acc[mf][nf][1];
            float v2 = acc[mf][nf][2], v3 = acc[mf][nf][3];
            if (roundOut) {
                v0 = roundtf(v0); v1 = roundtf(v1);
                v2 = roundtf(v2); v3 = roundtf(v3);
            }
            *(float2*)&C[(size_t)r * N + c]       = make_float2(v0, v1);
            *(float2*)&C[(size_t)(r + 8) * N + c] = make_float2(v2, v3);
        }
    }
}

// ---------------------------------------------------------------------------
// L2 norm over contiguous 64-float head vectors: one warp per vector.
// Output tf32-rounded (feeds attention mma directly).
// ---------------------------------------------------------------------------
__global__ void l2norm_kernel(float* __restrict__ d, int nvec) {
    int idx  = blockIdx.x * blockDim.x + threadIdx.x;
    int warp = idx >> 5;
    int lane = idx & 31;
    if (warp >= nvec) return;
    float2* p = reinterpret_cast<float2*>(d) + (size_t)warp * 32 + lane;
    float2 v = *p;
    float ss = v.x * v.x + v.y * v.y;
    #pragma unroll
    for (int o = 16; o; o >>= 1) ss += __shfl_xor_sync(0xffffffffu, ss, o);
    float sc = 1.0f / fmaxf(sqrtf(ss), 1e-12f);
    v.x = roundtf(v.x * sc); v.y = roundtf(v.y * sc);
    *p = v;
}

// ---------------------------------------------------------------------------
// Flash attention, tf32 mma, fixed-max softmax, 128-row Q tile.
// Inputs q/k/v pre-rounded tf32 -> only P needs cvt.
// Grid (LQ/128, H, B), 256 threads (8 warps: 4 row-slabs x 2 col-halves).
// Each warp: 32 q-rows (2 m-frags) x 32 k-cols (4 n-frags).
// ---------------------------------------------------------------------------
#define QPAD 68   // Q / P row stride (tf32 words)
#define VPAD 72   // V row stride

__global__ void attn_kernel(const float* __restrict__ Q,
                            const float* __restrict__ Kp,
                            const float* __restrict__ V,
                            const float* __restrict__ maskf,
                            const float* __restrict__ tau_p,
                            float* __restrict__ O) {
    extern __shared__ unsigned char smraw[];
    unsigned* Qs  = (unsigned*)smraw;                  // 128*QPAD
    unsigned* Ks  = Qs + 128 * QPAD;                   // 2 * 64*QPAD
    unsigned* Vs  = Ks + 2 * 64 * QPAD;                // 2 * 64*VPAD
    unsigned* Pb  = Vs + 2 * 64 * VPAD;                // 128*QPAD
    float*    Ms  = (float*)(Pb + 128 * QPAD);         // 2 * 64
    float*    lpart = Ms + 128;                        // 2 * 128

    int tid  = threadIdx.x;
    int wid  = tid >> 5, lane = tid & 31;
    int wm   = wid >> 1;          // 0..3 : 32-row slab
    int wn   = wid & 1;           // 0..1 : 32-col half
    int q0   = blockIdx.x * 128;
    int h    = blockIdx.y;
    int b    = blockIdx.z;

    float inv_tau = 1.0f / (*tau_p + 1e-6f);
    float MFIX = fabsf(inv_tau);   // scores bounded by |1/tau| (unit q,k)

    const float* Qbase = Q  + ((size_t)(b * LQQ + q0)) * DMODEL + h * DHEAD;
    const float* Kbase = Kp + ((size_t)b * LKK) * DMODEL + h * DHEAD;
    const float* Vbase = V  + ((size_t)b * LKK) * DMODEL + h * DHEAD;
    const float* Mbase = maskf + (size_t)b * LKK;

    // Q tile: 128 rows x 64 cols = 2048 float4 chunks, 8 per thread (cp.async)
    #pragma unroll
    for (int i = 0; i < 8; i++) {
        int fid = tid + i * 256;
        int r = fid >> 4, c4 = (fid & 15) << 2;
        cp_async16(&Qs[r * QPAD + c4], Qbase + (size_t)r * DMODEL + c4);
    }
    cp_commit();

    auto load_kv = [&](int k0, int buf) {
        #pragma unroll
        for (int i = 0; i < 4; i++) {
            int fid = tid + i * 256;
            int r = fid >> 4, c4 = (fid & 15) << 2;
            size_t g = (size_t)(k0 + r) * DMODEL + c4;
            cp_async16(&Ks[buf * 64 * QPAD + r * QPAD + c4], Kbase + g);
            cp_async16(&Vs[buf * 64 * VPAD + r * VPAD + c4], Vbase + g);
        }
        if (tid < 16) cp_async16(&Ms[buf * 64 + tid * 4], Mbase + k0 + tid * 4);
        cp_commit();
    };

    load_kv(0, 0);

    float oacc[2][4][4];
    #pragma unroll
    for (int m = 0; m < 2; m++)
        #pragma unroll
        for (int i = 0; i < 4; i++)
            #pragma unroll
            for (int j = 0; j < 4; j++) oacc[m][i][j] = 0.f;
    float lsum[2][2] = {};

    int rA = wm * 32 + (lane >> 2);   // base A-frag row (mf adds 16)
    int kA = lane & 3;                // A-frag k
    int nB = wn * 32 + (lane >> 2);   // B-frag n
    int scb = wn * 32 + (lane & 3) * 2;

    const int NT = LKK / 64;
    for (int kt = 0; kt < NT; kt++) {
        int cur = kt & 1;
        cp_wait<0>();
        __syncthreads();
        if (kt + 1 < NT) load_kv((kt + 1) * 64, cur ^ 1);

        const unsigned* Ksb = Ks + cur * 64 * QPAD;
        const unsigned* Vsb = Vs + cur * 64 * VPAD;
        const float*    Msb = Ms + cur * 64;

        // S = Q . K^T  (per warp: 32 rows x 32 cols)
        float sacc[2][4][4];
        #pragma unroll
        for (int m = 0; m < 2; m++)
            #pragma unroll
            for (int i = 0; i < 4; i++)
                #pragma unroll
                for (int j = 0; j < 4; j++) sacc[m][i][j] = 0.f;

        #pragma unroll
        for (int ks = 0; ks < 8; ks++) {
            int kb = ks * 8;
            unsigned bf[4][2];
            #pragma unroll
            for (int nf = 0; nf < 4; nf++) {
                bf[nf][0] = Ksb[(nB + nf * 8) * QPAD + kb + kA];
                bf[nf][1] = Ksb[(nB + nf * 8) * QPAD + kb + kA + 4];
            }
            #pragma unroll
            for (int mf = 0; mf < 2; mf++) {
                int r = rA + mf * 16;
                unsigned a0 = Qs[r * QPAD + kb + kA];
                unsigned a1 = Qs[(r + 8) * QPAD + kb + kA];
                unsigned a2 = Qs[r * QPAD + kb + kA + 4];
                unsigned a3 = Qs[(r + 8) * QPAD + kb + kA + 4];
                #pragma unroll
                for (int nf = 0; nf < 4; nf++)
                    mma_tf32(sacc[mf][nf], a0, a1, a2, a3, bf[nf][0], bf[nf][1]);
            }
        }

        // exp (fixed max) + mask, accumulate row sums, write P (tf32) to smem
        #pragma unroll
        for (int mf = 0; mf < 2; mf++) {
            int sr = rA + mf * 16;
            #pragma unroll
            for (int nf = 0; nf < 4; nf++) {
                int c = scb + nf * 8;
                float mk0 = Msb[c], mk1 = Msb[c + 1];
                float p00 = __expf(fminf(sacc[mf][nf][0] * inv_tau - MFIX, 0.f)) * mk0;
                float p01 = __expf(fminf(sacc[mf][nf][1] * inv_tau - MFIX, 0.f)) * mk1;
                float p10 = __expf(fminf(sacc[mf][nf][2] * inv_tau - MFIX, 0.f)) * mk0;
                float p11 = __expf(fminf(sacc[mf][nf][3] * inv_tau - MFIX, 0.f)) * mk1;
                lsum[mf][0] += p00 + p01;
                lsum[mf][1] += p10 + p11;
                *(uint2*)&Pb[sr * QPAD + c]       = make_uint2(f2tf(p00), f2tf(p01));
                *(uint2*)&Pb[(sr + 8) * QPAD + c] = make_uint2(f2tf(p10), f2tf(p11));
            }
        }
        __syncthreads();   // Pb complete before PV mma

        // O += P . V
        #pragma unroll
        for (int ks = 0; ks < 8; ks++) {
            int kb = ks * 8;
            unsigned bf[4][2];
            #pragma unroll
            for (int nf = 0; nf < 4; nf++) {
                bf[nf][0] = Vsb[(kb + kA) * VPAD + nB + nf * 8];
                bf[nf][1] = Vsb[(kb + kA + 4) * VPAD + nB + nf * 8];
            }
            #pragma unroll
            for (int mf = 0; mf < 2; mf++) {
                int r = rA + mf * 16;
                unsigned a0 = Pb[r * QPAD + kb + kA];
                unsigned a1 = Pb[(r + 8) * QPAD + kb + kA];
                unsigned a2 = Pb[r * QPAD + kb + kA + 4];
                unsigned a3 = Pb[(r + 8) * QPAD + kb + kA + 4];
                #pragma unroll
                for (int nf = 0; nf < 4; nf++)
                    mma_tf32(oacc[mf][nf], a0, a1, a2, a3, bf[nf][0], bf[nf][1]);
            }
        }
    }

    // combine row sums: quad-reduce then across the two wn halves via smem
    #pragma unroll
    for (int mf = 0; mf < 2; mf++) {
        lsum[mf][0] += __shfl_xor_sync(0xffffffffu, lsum[mf][0], 1);
        lsum[mf][0] += __shfl_xor_sync(0xffffffffu, lsum[mf][0], 2);
        lsum[mf][1] += __shfl_xor_sync(0xffffffffu, lsum[mf][1], 1);
        lsum[mf][1] += __shfl_xor_sync(0xffffffffu, lsum[mf][1], 2);
    }
    __syncthreads();
    if ((lane & 3) == 0) {
        #pragma unroll
        for (int mf = 0; mf < 2; mf++) {
            int r = rA + mf * 16;
            lpart[wn * 128 + r]     = lsum[mf][0];
            lpart[wn * 128 + r + 8] = lsum[mf][1];
        }
    }
    __syncthreads();

    // Epilogue: divide by l, tf32-round (feeds final GEMM), store
    #pragma unroll
    for (int mf = 0; mf < 2; mf++) {
        int r0 = rA + mf * 16;
        float li0 = 1.0f / (lpart[r0]     + lpart[128 + r0]);
        float li1 = 1.0f / (lpart[r0 + 8] + lpart[128 + r0 + 8]);
        int gcol = h * DHEAD + wn * 32 + (lane & 3) * 2;
        #pragma unroll
        for (int nf = 0; nf < 4; nf++) {
            size_t base0 = ((size_t)(b * LQQ + q0 + r0)) * DMODEL + gcol + nf * 8;
            size_t base1 = ((size_t)(b * LQQ + q0 + r0 + 8)) * DMODEL + gcol + nf * 8;
            *(float2*)&O[base0] = make_float2(roundtf(oacc[mf][nf][0] * li0),
                                              roundtf(oacc[mf][nf][1] * li0));
            *(float2*)&O[base1] = make_float2(roundtf(oacc[mf][nf][2] * li1),
                                              roundtf(oacc[mf][nf][3] * li1));
        }
    }
}

// ---------------------------------------------------------------------------
// Launcher
// ---------------------------------------------------------------------------
extern "C" void kernel_launch(void* const* d_in, const int* in_sizes, int n_in,
                              void* d_out, int out_size) {
    const float* x     = (const float*)d_in[0];
    const float* ctx   = (const float*)d_in[1];
    const void*  mask  = d_in[2];
    const float* lnqw  = (const float*)d_in[3];
    const float* lnqb  = (const float*)d_in[4];
    const float* lncw  = (const float*)d_in[5];
    const float* lncb  = (const float*)d_in[6];
    const float* Wq    = (const float*)d_in[7];
    const float* Wk    = (const float*)d_in[8];
    const float* Wv    = (const float*)d_in[9];
    const float* Wo    = (const float*)d_in[10];
    const float* taup  = (const float*)d_in[11];
    float* out = (float*)d_out;

    float *qln, *kvln, *q, *k, *v, *ao, *maskf, *wq, *wk, *wv, *wo;
    cudaGetSymbolAddress((void**)&qln,   g_qln);
    cudaGetSymbolAddress((void**)&kvln,  g_kvln);
    cudaGetSymbolAddress((void**)&q,     g_q);
    cudaGetSymbolAddress((void**)&k,     g_k);
    cudaGetSymbolAddress((void**)&v,     g_v);
    cudaGetSymbolAddress((void**)&ao,    g_ao);
    cudaGetSymbolAddress((void**)&maskf, g_maskf);
    cudaGetSymbolAddress((void**)&wq,    g_wq);
    cudaGetSymbolAddress((void**)&wk,    g_wk);
    cudaGetSymbolAddress((void**)&wv,    g_wv);
    cudaGetSymbolAddress((void**)&wo,    g_wo);

    // attention dynamic smem
    const int smem_attn = (int)((128 * QPAD + 2 * 64 * QPAD + 128 * QPAD) * 4
                              + 2 * 64 * VPAD * 4
                              + (128 + 256) * 4);
    cudaFuncSetAttribute(attn_kernel, cudaFuncAttributeMaxDynamicSharedMemorySize, smem_attn);

    detect_mask_kernel<<<1, 256>>>((const unsigned char*)mask);
    maskf_kernel<<<(BATCH * LKK + 255) / 256, 256>>>(mask);

    // round weights to tf32 once per call
    int n4 = DMODEL * DMODEL / 4;
    round_tf32_kernel<<<n4 / 256, 256>>>((const float4*)Wq, (float4*)wq, n4);
    round_tf32_kernel<<<n4 / 256, 256>>>((const float4*)Wk, (float4*)wk, n4);
    round_tf32_kernel<<<n4 / 256, 256>>>((const float4*)Wv, (float4*)wv, n4);
    round_tf32_kernel<<<n4 / 256, 256>>>((const float4*)Wo, (float4*)wo, n4);

    ln_kernel<<<BATCH * LQQ, 256>>>(x,   lnqw, lnqb, qln);
    ln_kernel<<<BATCH * LKK, 256>>>(ctx, lncw, lncb, kvln);

    dim3 gg(DMODEL / TBN, (BATCH * LQQ) / TBM);
    tgemm_kernel<<<gg, 256>>>(qln,  wq, q, BATCH * LQQ, DMODEL, DMODEL, 0);
    tgemm_kernel<<<gg, 256>>>(kvln, wk, k, BATCH * LKK, DMODEL, DMODEL, 0);
    tgemm_kernel<<<gg, 256>>>(kvln, wv, v, BATCH * LKK, DMODEL, DMODEL, 1);

    int nvec = BATCH * LQQ * NHEAD;
    l2norm_kernel<<<(nvec * 32) / 256, 256>>>(q, nvec);
    l2norm_kernel<<<(nvec * 32) / 256, 256>>>(k, nvec);

    attn_kernel<<<dim3(LQQ / 128, NHEAD, BATCH), 256, smem_attn>>>(q, k, v, maskf, taup, ao);

    tgemm_kernel<<<gg, 256>>>(ao, wo, out, BATCH * LQQ, DMODEL, DMODEL, 0);
}

// round 5
// speedup vs baseline: 3.6507x; 1.0497x over previous
#include <cuda_runtime.h>
#include <math.h>

// Problem constants
#define BATCH 4
#define LQQ   2048
#define LKK   2048
#define DMODEL 1024
#define NHEAD 16
#define DHEAD 64

// Scratch (static device arrays -- no runtime allocation allowed)
__device__ float g_qln [BATCH * LQQ * DMODEL];
__device__ float g_kvln[BATCH * LKK * DMODEL];
__device__ float g_q   [BATCH * LQQ * DMODEL];
__device__ float g_k   [BATCH * LKK * DMODEL];
__device__ float g_v   [BATCH * LKK * DMODEL];
__device__ float g_ao  [BATCH * LQQ * DMODEL];
__device__ float g_wq  [DMODEL * DMODEL];
__device__ float g_wk  [DMODEL * DMODEL];
__device__ float g_wv  [DMODEL * DMODEL];
__device__ float g_wo  [DMODEL * DMODEL];
__device__ float g_maskf[BATCH * LKK];   // 0.0 = masked, 1.0 = keep
__device__ int   g_mask_mode;            // 0=uint8, 1=int32, 2=float32

// ---------------------------------------------------------------------------
// tf32 / cp.async helpers
// ---------------------------------------------------------------------------
__device__ __forceinline__ unsigned f2tf(float f) {
    unsigned u;
    asm("cvt.rna.tf32.f32 %0, %1;" : "=r"(u) : "f"(f));
    return u;
}
__device__ __forceinline__ float roundtf(float f) {
    return __uint_as_float(f2tf(f));
}

__device__ __forceinline__ void mma_tf32(float c[4],
                                         unsigned a0, unsigned a1, unsigned a2, unsigned a3,
                                         unsigned b0, unsigned b1) {
    asm volatile(
        "mma.sync.aligned.m16n8k8.row.col.f32.tf32.tf32.f32 "
        "{%0,%1,%2,%3},{%4,%5,%6,%7},{%8,%9},{%0,%1,%2,%3};"
        : "+f"(c[0]), "+f"(c[1]), "+f"(c[2]), "+f"(c[3])
        : "r"(a0), "r"(a1), "r"(a2), "r"(a3), "r"(b0), "r"(b1));
}

__device__ __forceinline__ void cp_async16(void* smem_dst, const void* gmem_src) {
    unsigned sa = (unsigned)__cvta_generic_to_shared(smem_dst);
    asm volatile("cp.async.cg.shared.global [%0], [%1], 16;" :: "r"(sa), "l"(gmem_src));
}
__device__ __forceinline__ void cp_commit() {
    asm volatile("cp.async.commit_group;");
}
template <int N>
__device__ __forceinline__ void cp_wait() {
    asm volatile("cp.async.wait_group %0;" :: "n"(N));
}

// ---------------------------------------------------------------------------
// Mask dtype detection (bool array may arrive as u8/i32/f32)
// ---------------------------------------------------------------------------
__global__ void detect_mask_kernel(const unsigned char* __restrict__ m) {
    __shared__ int nz[4];
    if (threadIdx.x < 4) nz[threadIdx.x] = 0;
    __syncthreads();
    int loc = 0;
    for (int i = threadIdx.x; i < 8192; i += blockDim.x)
        if (m[i]) loc = 1;
    if (loc) atomicOr(&nz[threadIdx.x & 3], 1);
    __syncthreads();
    if (threadIdx.x == 0) {
        int mode;
        int tot = nz[0] | nz[1] | nz[2] | nz[3];
        if (!tot)                          mode = 0;
        else if (!(nz[1] | nz[2] | nz[3])) mode = 1; // int32 LE
        else if (!(nz[0] | nz[1]))         mode = 2; // float32 (0x3F800000)
        else                               mode = 0; // uint8/bool
        g_mask_mode = mode;
    }
}

// Convert mask (any dtype) into multiplicative float mask: 0 = masked, 1 = keep
__global__ void maskf_kernel(const void* __restrict__ m) {
    int i = blockIdx.x * blockDim.x + threadIdx.x;
    if (i >= BATCH * LKK) return;
    int mode = g_mask_mode;
    bool mm = (mode == 0) ? (((const unsigned char*)m)[i] != 0)
            : (mode == 1) ? (((const int*)m)[i] != 0)
                          : (((const float*)m)[i] != 0.f);
    g_maskf[i] = mm ? 0.f : 1.f;
}

// Round fp32 array to tf32 (rna), float4 vectorized. n4 = count/4.
__global__ void round_tf32_kernel(const float4* __restrict__ in,
                                  float4* __restrict__ out, int n4) {
    int i = blockIdx.x * blockDim.x + threadIdx.x;
    if (i >= n4) return;
    float4 v = in[i];
    v.x = roundtf(v.x); v.y = roundtf(v.y);
    v.z = roundtf(v.z); v.w = roundtf(v.w);
    out[i] = v;
}

// ---------------------------------------------------------------------------
// LayerNorm: one block per row of 1024, 256 threads, float4 paths.
// Output is tf32-rounded (feeds tensor-core GEMMs directly).
// ---------------------------------------------------------------------------
__global__ void ln_kernel(const float* __restrict__ x,
                          const float* __restrict__ w,
                          const float* __restrict__ bia,
                          float* __restrict__ out) {
    int row = blockIdx.x;
    int tid = threadIdx.x;
    const float4* xr = reinterpret_cast<const float4*>(x + (size_t)row * DMODEL);
    float4 a = xr[tid];
    float s  = a.x + a.y + a.z + a.w;
    float ss = a.x * a.x + a.y * a.y + a.z * a.z + a.w * a.w;

    __shared__ float rs[8], rss[8], stats[2];
    #pragma unroll
    for (int o = 16; o; o >>= 1) {
        s  += __shfl_xor_sync(0xffffffffu, s,  o);
        ss += __shfl_xor_sync(0xffffffffu, ss, o);
    }
    int wid = tid >> 5, lane = tid & 31;
    if (!lane) { rs[wid] = s; rss[wid] = ss; }
    __syncthreads();
    if (tid == 0) {
        float S = 0.f, SS = 0.f;
        #pragma unroll
        for (int i = 0; i < 8; i++) { S += rs[i]; SS += rss[i]; }
        float mean = S * (1.0f / DMODEL);
        float var  = SS * (1.0f / DMODEL) - mean * mean;
        stats[0] = mean;
        stats[1] = rsqrtf(var + 1e-5f);
    }
    __syncthreads();
    float mean = stats[0], rstd = stats[1];
    float4 wv = reinterpret_cast<const float4*>(w)[tid];
    float4 bv = reinterpret_cast<const float4*>(bia)[tid];
    float4 o;
    o.x = roundtf((a.x - mean) * rstd * wv.x + bv.x);
    o.y = roundtf((a.y - mean) * rstd * wv.y + bv.y);
    o.z = roundtf((a.z - mean) * rstd * wv.z + bv.z);
    o.w = roundtf((a.w - mean) * rstd * wv.w + bv.w);
    reinterpret_cast<float4*>(out + (size_t)row * DMODEL)[tid] = o;
}

// ---------------------------------------------------------------------------
// tf32 tensor-core GEMM with cp.async 3-stage pipeline (dynamic smem).
// Inputs PRE-ROUNDED to tf32 -> zero cvt in the inner loop.
// C[M,N] = A[M,K] @ B[K,N], row-major. 128x128x16 tiles, 256 threads.
// ---------------------------------------------------------------------------
#define TBM 128
#define TBN 128
#define TBK 16
#define APAD 20
#define BPAD 136
#define ASZ (TBM * APAD)
#define BSZ (TBK * BPAD)

__global__ __launch_bounds__(256) void tgemm_kernel(
        const float* __restrict__ A,
        const float* __restrict__ Bm,
        float* __restrict__ C,
        int M, int N, int K, int roundOut) {
    extern __shared__ float gsm[];
    float* As = gsm;            // 3 * ASZ
    float* Bs = gsm + 3 * ASZ;  // 3 * BSZ

    int tid = threadIdx.x;
    int wid = tid >> 5, lane = tid & 31;
    int wm = wid >> 2, wn = wid & 3;                // 2 x 4 warp grid
    int m0 = blockIdx.y * TBM, n0 = blockIdx.x * TBN;

    float acc[4][4][4];
    #pragma unroll
    for (int i = 0; i < 4; i++)
        #pragma unroll
        for (int j = 0; j < 4; j++)
            #pragma unroll
            for (int t = 0; t < 4; t++) acc[i][j][t] = 0.f;

    int ar = tid >> 2;             // 0..63 (+64)
    int ak = (tid & 3) << 2;       // 0,4,8,12
    int br = tid >> 5;             // 0..7 (+8)
    int bc = (tid & 31) << 2;      // 0..124

    const float* Ag = A + (size_t)(m0 + ar) * K + ak;
    const float* Bg = Bm + (size_t)br * N + n0 + bc;

    int arow = wm * 64 + (lane >> 2);
    int acol = lane & 3;
    int bn   = wn * 32 + (lane >> 2);

    auto load_tile = [&](int kt, int buf) {
        int k0 = kt * TBK;
        cp_async16(&As[buf * ASZ + ar * APAD + ak],        Ag + k0);
        cp_async16(&As[buf * ASZ + (ar + 64) * APAD + ak], Ag + (size_t)64 * K + k0);
        cp_async16(&Bs[buf * BSZ + br * BPAD + bc],        Bg + (size_t)k0 * N);
        cp_async16(&Bs[buf * BSZ + (br + 8) * BPAD + bc],  Bg + (size_t)(k0 + 8) * N);
        cp_commit();
    };

    int nt = K / TBK;
    load_tile(0, 0);
    load_tile(1, 1);

    for (int kt = 0; kt < nt; kt++) {
        int cur = kt % 3;
        if (kt + 2 < nt) cp_wait<1>(); else cp_wait<0>();
        __syncthreads();
        if (kt + 2 < nt) load_tile(kt + 2, (kt + 2) % 3);

        const unsigned* Asb = (const unsigned*)(As + cur * ASZ);
        const unsigned* Bsb = (const unsigned*)(Bs + cur * BSZ);
        #pragma unroll
        for (int ks = 0; ks < 2; ks++) {
            int kb = ks * 8;
            unsigned af[4][4];
            #pragma unroll
            for (int mf = 0; mf < 4; mf++) {
                int r = arow + mf * 16;
                af[mf][0] = Asb[r * APAD + kb + acol];
                af[mf][1] = Asb[(r + 8) * APAD + kb + acol];
                af[mf][2] = Asb[r * APAD + kb + acol + 4];
                af[mf][3] = Asb[(r + 8) * APAD + kb + acol + 4];
            }
            unsigned bf[4][2];
            #pragma unroll
            for (int nf = 0; nf < 4; nf++) {
                bf[nf][0] = Bsb[(kb + acol) * BPAD + bn + nf * 8];
                bf[nf][1] = Bsb[(kb + 4 + acol) * BPAD + bn + nf * 8];
            }
            #pragma unroll
            for (int mf = 0; mf < 4; mf++)
                #pragma unroll
                for (int nf = 0; nf < 4; nf++)
                    mma_tf32(acc[mf][nf], af[mf][0], af[mf][1], af[mf][2], af[mf][3],
                             bf[nf][0], bf[nf][1]);
        }
    }

    int crow = m0 + wm * 64 + (lane >> 2);
    int ccol = n0 + wn * 32 + (lane & 3) * 2;
    #pragma unroll
    for (int mf = 0; mf < 4; mf++) {
        #pragma unroll
        for (int nf = 0; nf < 4; nf++) {
            int r = crow + mf * 16;
            int c = ccol + nf * 8;
            float v0 = acc[mf][nf][0], v1 = acc[mf][nf][1];
            float v2 = acc[mf][nf][2], v3 = acc[mf][nf][3];
            if (roundOut) {
                v0 = roundtf(v0); v1 = roundtf(v1);
                v2 = roundtf(v2); v3 = roundtf(v3);
            }
            *(float2*)&C[(size_t)r * N + c]       = make_float2(v0, v1);
            *(float2*)&C[(size_t)(r + 8) * N + c] = make_float2(v2, v3);
        }
    }
}

// ---------------------------------------------------------------------------
// L2 norm over contiguous 64-float head vectors: one warp per vector.
// Output tf32-rounded (feeds attention mma directly).
// ---------------------------------------------------------------------------
__global__ void l2norm_kernel(float* __restrict__ d, int nvec) {
    int idx  = blockIdx.x * blockDim.x + threadIdx.x;
    int warp = idx >> 5;
    int lane = idx & 31;
    if (warp >= nvec) return;
    float2* p = reinterpret_cast<float2*>(d) + (size_t)warp * 32 + lane;
    float2 v = *p;
    float ss = v.x * v.x + v.y * v.y;
    #pragma unroll
    for (int o = 16; o; o >>= 1) ss += __shfl_xor_sync(0xffffffffu, ss, o);
    float sc = 1.0f / fmaxf(sqrtf(ss), 1e-12f);
    v.x = roundtf(v.x * sc); v.y = roundtf(v.y * sc);
    *p = v;
}

// ---------------------------------------------------------------------------
// Flash attention, tf32 mma, fixed-max softmax, 256-row Q tile.
// Warp tile 64 q-rows x 32 k-cols (4 m-frags x 4 n-frags): B-frags reused 4x.
// Grid (LQ/256, H, B), 256 threads (8 warps: 4 row-slabs x 2 col-halves).
// ---------------------------------------------------------------------------
#define QROWS 256
#define QPAD 68   // Q / P row stride (tf32 words)
#define VPAD 72   // V row stride

__global__ __launch_bounds__(256, 1) void attn_kernel(
        const float* __restrict__ Q,
        const float* __restrict__ Kp,
        const float* __restrict__ V,
        const float* __restrict__ maskf,
        const float* __restrict__ tau_p,
        float* __restrict__ O) {
    extern __shared__ unsigned char smraw[];
    unsigned* Qs  = (unsigned*)smraw;                  // QROWS*QPAD
    unsigned* Ks  = Qs + QROWS * QPAD;                 // 2 * 64*QPAD
    unsigned* Vs  = Ks + 2 * 64 * QPAD;                // 2 * 64*VPAD
    unsigned* Pb  = Vs + 2 * 64 * VPAD;                // QROWS*QPAD
    float*    Ms  = (float*)(Pb + QROWS * QPAD);       // 2 * 64
    float*    lpart = Ms + 128;                        // 2 * QROWS

    int tid  = threadIdx.x;
    int wid  = tid >> 5, lane = tid & 31;
    int wm   = wid >> 1;          // 0..3 : 64-row slab
    int wn   = wid & 1;           // 0..1 : 32-col half
    int q0   = blockIdx.x * QROWS;
    int h    = blockIdx.y;
    int b    = blockIdx.z;

    float inv_tau = 1.0f / (*tau_p + 1e-6f);
    float MFIX = fabsf(inv_tau);   // scores bounded by |1/tau| (unit q,k)

    const float* Qbase = Q  + ((size_t)(b * LQQ + q0)) * DMODEL + h * DHEAD;
    const float* Kbase = Kp + ((size_t)b * LKK) * DMODEL + h * DHEAD;
    const float* Vbase = V  + ((size_t)b * LKK) * DMODEL + h * DHEAD;
    const float* Mbase = maskf + (size_t)b * LKK;

    // Q tile: 256 rows x 64 cols = 4096 float4 chunks, 16 per thread
    #pragma unroll
    for (int i = 0; i < 16; i++) {
        int fid = tid + i * 256;
        int r = fid >> 4, c4 = (fid & 15) << 2;
        cp_async16(&Qs[r * QPAD + c4], Qbase + (size_t)r * DMODEL + c4);
    }
    cp_commit();

    auto load_kv = [&](int k0, int buf) {
        #pragma unroll
        for (int i = 0; i < 4; i++) {
            int fid = tid + i * 256;
            int r = fid >> 4, c4 = (fid & 15) << 2;
            size_t g = (size_t)(k0 + r) * DMODEL + c4;
            cp_async16(&Ks[buf * 64 * QPAD + r * QPAD + c4], Kbase + g);
            cp_async16(&Vs[buf * 64 * VPAD + r * VPAD + c4], Vbase + g);
        }
        if (tid < 16) cp_async16(&Ms[buf * 64 + tid * 4], Mbase + k0 + tid * 4);
        cp_commit();
    };

    load_kv(0, 0);

    float oacc[4][4][4];
    #pragma unroll
    for (int m = 0; m < 4; m++)
        #pragma unroll
        for (int i = 0; i < 4; i++)
            #pragma unroll
            for (int j = 0; j < 4; j++) oacc[m][i][j] = 0.f;
    float lsum[4][2] = {};

    int rA = wm * 64 + (lane >> 2);   // base A-frag row (mf adds 16)
    int kA = lane & 3;                // A-frag k
    int nB = wn * 32 + (lane >> 2);   // B-frag n
    int scb = wn * 32 + (lane & 3) * 2;

    const int NT = LKK / 64;
    for (int kt = 0; kt < NT; kt++) {
        int cur = kt & 1;
        cp_wait<0>();
        __syncthreads();
        if (kt + 1 < NT) load_kv((kt + 1) * 64, cur ^ 1);

        const unsigned* Ksb = Ks + cur * 64 * QPAD;
        const unsigned* Vsb = Vs + cur * 64 * VPAD;
        const float*    Msb = Ms + cur * 64;

        // S = Q . K^T  (per warp: 64 rows x 32 cols)
        float sacc[4][4][4];
        #pragma unroll
        for (int m = 0; m < 4; m++)
            #pragma unroll
            for (int i = 0; i < 4; i++)
                #pragma unroll
                for (int j = 0; j < 4; j++) sacc[m][i][j] = 0.f;

        #pragma unroll
        for (int ks = 0; ks < 8; ks++) {
            int kb = ks * 8;
            unsigned bf[4][2];
            #pragma unroll
            for (int nf = 0; nf < 4; nf++) {
                bf[nf][0] = Ksb[(nB + nf * 8) * QPAD + kb + kA];
                bf[nf][1] = Ksb[(nB + nf * 8) * QPAD + kb + kA + 4];
            }
            #pragma unroll
            for (int mf = 0; mf < 4; mf++) {
                int r = rA + mf * 16;
                unsigned a0 = Qs[r * QPAD + kb + kA];
                unsigned a1 = Qs[(r + 8) * QPAD + kb + kA];
                unsigned a2 = Qs[r * QPAD + kb + kA + 4];
                unsigned a3 = Qs[(r + 8) * QPAD + kb + kA + 4];
                #pragma unroll
                for (int nf = 0; nf < 4; nf++)
                    mma_tf32(sacc[mf][nf], a0, a1, a2, a3, bf[nf][0], bf[nf][1]);
            }
        }

        // exp (fixed max) + mask, accumulate row sums, write P (tf32) to smem
        #pragma unroll
        for (int mf = 0; mf < 4; mf++) {
            int sr = rA + mf * 16;
            #pragma unroll
            for (int nf = 0; nf < 4; nf++) {
                int c = scb + nf * 8;
                float mk0 = Msb[c], mk1 = Msb[c + 1];
                float p00 = __expf(fminf(sacc[mf][nf][0] * inv_tau - MFIX, 0.f)) * mk0;
                float p01 = __expf(fminf(sacc[mf][nf][1] * inv_tau - MFIX, 0.f)) * mk1;
                float p10 = __expf(fminf(sacc[mf][nf][2] * inv_tau - MFIX, 0.f)) * mk0;
                float p11 = __expf(fminf(sacc[mf][nf][3] * inv_tau - MFIX, 0.f)) * mk1;
                lsum[mf][0] += p00 + p01;
                lsum[mf][1] += p10 + p11;
                *(uint2*)&Pb[sr * QPAD + c]       = make_uint2(f2tf(p00), f2tf(p01));
                *(uint2*)&Pb[(sr + 8) * QPAD + c] = make_uint2(f2tf(p10), f2tf(p11));
            }
        }
        __syncthreads();   // Pb complete before PV mma

        // O += P . V
        #pragma unroll
        for (int ks = 0; ks < 8; ks++) {
            int kb = ks * 8;
            unsigned bf[4][2];
            #pragma unroll
            for (int nf = 0; nf < 4; nf++) {
                bf[nf][0] = Vsb[(kb + kA) * VPAD + nB + nf * 8];
                bf[nf][1] = Vsb[(kb + kA + 4) * VPAD + nB + nf * 8];
            }
            #pragma unroll
            for (int mf = 0; mf < 4; mf++) {
                int r = rA + mf * 16;
                unsigned a0 = Pb[r * QPAD + kb + kA];
                unsigned a1 = Pb[(r + 8) * QPAD + kb + kA];
                unsigned a2 = Pb[r * QPAD + kb + kA + 4];
                unsigned a3 = Pb[(r + 8) * QPAD + kb + kA + 4];
                #pragma unroll
                for (int nf = 0; nf < 4; nf++)
                    mma_tf32(oacc[mf][nf], a0, a1, a2, a3, bf[nf][0], bf[nf][1]);
            }
        }
    }

    // combine row sums: quad-reduce then across the two wn halves via smem
    #pragma unroll
    for (int mf = 0; mf < 4; mf++) {
        lsum[mf][0] += __shfl_xor_sync(0xffffffffu, lsum[mf][0], 1);
        lsum[mf][0] += __shfl_xor_sync(0xffffffffu, lsum[mf][0], 2);
        lsum[mf][1] += __shfl_xor_sync(0xffffffffu, lsum[mf][1], 1);
        lsum[mf][1] += __shfl_xor_sync(0xffffffffu, lsum[mf][1], 2);
    }
    __syncthreads();
    if ((lane & 3) == 0) {
        #pragma unroll
        for (int mf = 0; mf < 4; mf++) {
            int r = rA + mf * 16;
            lpart[wn * QROWS + r]     = lsum[mf][0];
            lpart[wn * QROWS + r + 8] = lsum[mf][1];
        }
    }
    __syncthreads();

    // Epilogue: divide by l, tf32-round (feeds final GEMM), store
    #pragma unroll
    for (int mf = 0; mf < 4; mf++) {
        int r0 = rA + mf * 16;
        float li0 = 1.0f / (lpart[r0]     + lpart[QROWS + r0]);
        float li1 = 1.0f / (lpart[r0 + 8] + lpart[QROWS + r0 + 8]);
        int gcol = h * DHEAD + wn * 32 + (lane & 3) * 2;
        #pragma unroll
        for (int nf = 0; nf < 4; nf++) {
            size_t base0 = ((size_t)(b * LQQ + q0 + r0)) * DMODEL + gcol + nf * 8;
            size_t base1 = ((size_t)(b * LQQ + q0 + r0 + 8)) * DMODEL + gcol + nf * 8;
            *(float2*)&O[base0] = make_float2(roundtf(oacc[mf][nf][0] * li0),
                                              roundtf(oacc[mf][nf][1] * li0));
            *(float2*)&O[base1] = make_float2(roundtf(oacc[mf][nf][2] * li1),
                                              roundtf(oacc[mf][nf][3] * li1));
        }
    }
}

// ---------------------------------------------------------------------------
// Launcher
// ---------------------------------------------------------------------------
extern "C" void kernel_launch(void* const* d_in, const int* in_sizes, int n_in,
                              void* d_out, int out_size) {
    const float* x     = (const float*)d_in[0];
    const float* ctx   = (const float*)d_in[1];
    const void*  mask  = d_in[2];
    const float* lnqw  = (const float*)d_in[3];
    const float* lnqb  = (const float*)d_in[4];
    const float* lncw  = (const float*)d_in[5];
    const float* lncb  = (const float*)d_in[6];
    const float* Wq    = (const float*)d_in[7];
    const float* Wk    = (const float*)d_in[8];
    const float* Wv    = (const float*)d_in[9];
    const float* Wo    = (const float*)d_in[10];
    const float* taup  = (const float*)d_in[11];
    float* out = (float*)d_out;

    float *qln, *kvln, *q, *k, *v, *ao, *maskf, *wq, *wk, *wv, *wo;
    cudaGetSymbolAddress((void**)&qln,   g_qln);
    cudaGetSymbolAddress((void**)&kvln,  g_kvln);
    cudaGetSymbolAddress((void**)&q,     g_q);
    cudaGetSymbolAddress((void**)&k,     g_k);
    cudaGetSymbolAddress((void**)&v,     g_v);
    cudaGetSymbolAddress((void**)&ao,    g_ao);
    cudaGetSymbolAddress((void**)&maskf, g_maskf);
    cudaGetSymbolAddress((void**)&wq,    g_wq);
    cudaGetSymbolAddress((void**)&wk,    g_wk);
    cudaGetSymbolAddress((void**)&wv,    g_wv);
    cudaGetSymbolAddress((void**)&wo,    g_wo);

    // GEMM dynamic smem (3-stage)
    const int smem_gemm = (int)((3 * ASZ + 3 * BSZ) * sizeof(float));
    cudaFuncSetAttribute(tgemm_kernel, cudaFuncAttributeMaxDynamicSharedMemorySize, smem_gemm);

    // attention dynamic smem
    const int smem_attn = (int)((QROWS * QPAD + 2 * 64 * QPAD + QROWS * QPAD) * 4
                              + 2 * 64 * VPAD * 4
                              + (128 + 2 * QROWS) * 4);
    cudaFuncSetAttribute(attn_kernel, cudaFuncAttributeMaxDynamicSharedMemorySize, smem_attn);

    detect_mask_kernel<<<1, 256>>>((const unsigned char*)mask);
    maskf_kernel<<<(BATCH * LKK + 255) / 256, 256>>>(mask);

    // round weights to tf32 once per call
    int n4 = DMODEL * DMODEL / 4;
    round_tf32_kernel<<<n4 / 256, 256>>>((const float4*)Wq, (float4*)wq, n4);
    round_tf32_kernel<<<n4 / 256, 256>>>((const float4*)Wk, (float4*)wk, n4);
    round_tf32_kernel<<<n4 / 256, 256>>>((const float4*)Wv, (float4*)wv, n4);
    round_tf32_kernel<<<n4 / 256, 256>>>((const float4*)Wo, (float4*)wo, n4);

    ln_kernel<<<BATCH * LQQ, 256>>>(x,   lnqw, lnqb, qln);
    ln_kernel<<<BATCH * LKK, 256>>>(ctx, lncw, lncb, kvln);

    dim3 gg(DMODEL / TBN, (BATCH * LQQ) / TBM);
    tgemm_kernel<<<gg, 256, smem_gemm>>>(qln,  wq, q, BATCH * LQQ, DMODEL, DMODEL, 0);
    tgemm_kernel<<<gg, 256, smem_gemm>>>(kvln, wk, k, BATCH * LKK, DMODEL, DMODEL, 0);
    tgemm_kernel<<<gg, 256, smem_gemm>>>(kvln, wv, v, BATCH * LKK, DMODEL, DMODEL, 1);

    int nvec = BATCH * LQQ * NHEAD;
    l2norm_kernel<<<(nvec * 32) / 256, 256>>>(q, nvec);
    l2norm_kernel<<<(nvec * 32) / 256, 256>>>(k, nvec);

    attn_kernel<<<dim3(LQQ / QROWS, NHEAD, BATCH), 256, smem_attn>>>(q, k, v, maskf, taup, ao);

    tgemm_kernel<<<gg, 256, smem_gemm>>>(ao, wo, out, BATCH * LQQ, DMODEL, DMODEL, 0);
}

// round 6
// speedup vs baseline: 5.8833x; 1.6116x over previous
#include <cuda_runtime.h>
#include <cuda_fp16.h>
#include <math.h>

// Problem constants
#define BATCH 4
#define LQQ   2048
#define LKK   2048
#define DMODEL 1024
#define NHEAD 16
#define DHEAD 64

// Scratch (static device arrays -- no runtime allocation allowed)
__device__ __half g_qln [BATCH * LQQ * DMODEL];
__device__ __half g_kvln[BATCH * LKK * DMODEL];
__device__ __half g_q   [BATCH * LQQ * DMODEL];
__device__ __half g_k   [BATCH * LKK * DMODEL];
__device__ __half g_vt  [BATCH * NHEAD * DHEAD * LKK];  // [b][h][d][kv]
__device__ __half g_ao  [BATCH * LQQ * DMODEL];
__device__ __half g_wq  [DMODEL * DMODEL];  // transposed [N][K]
__device__ __half g_wk  [DMODEL * DMODEL];
__device__ __half g_wv  [DMODEL * DMODEL];
__device__ __half g_wo  [DMODEL * DMODEL];
__device__ float  g_maskf[BATCH * LKK];   // 0.0 = masked, 1.0 = keep
__device__ int    g_mask_mode;            // 0=uint8, 1=int32, 2=float32

// ---------------------------------------------------------------------------
// mma / cp.async helpers
// ---------------------------------------------------------------------------
__device__ __forceinline__ void mma_f16(float c[4],
                                        unsigned a0, unsigned a1, unsigned a2, unsigned a3,
                                        unsigned b0, unsigned b1) {
    asm volatile(
        "mma.sync.aligned.m16n8k16.row.col.f32.f16.f16.f32 "
        "{%0,%1,%2,%3},{%4,%5,%6,%7},{%8,%9},{%0,%1,%2,%3};"
        : "+f"(c[0]), "+f"(c[1]), "+f"(c[2]), "+f"(c[3])
        : "r"(a0), "r"(a1), "r"(a2), "r"(a3), "r"(b0), "r"(b1));
}

__device__ __forceinline__ void cp_async16(void* smem_dst, const void* gmem_src) {
    unsigned sa = (unsigned)__cvta_generic_to_shared(smem_dst);
    asm volatile("cp.async.cg.shared.global [%0], [%1], 16;" :: "r"(sa), "l"(gmem_src));
}
__device__ __forceinline__ void cp_commit() {
    asm volatile("cp.async.commit_group;");
}
template <int N>
__device__ __forceinline__ void cp_wait() {
    asm volatile("cp.async.wait_group %0;" :: "n"(N));
}

// ---------------------------------------------------------------------------
// Mask dtype detection (bool array may arrive as u8/i32/f32)
// ---------------------------------------------------------------------------
__global__ void detect_mask_kernel(const unsigned char* __restrict__ m) {
    __shared__ int nz[4];
    if (threadIdx.x < 4) nz[threadIdx.x] = 0;
    __syncthreads();
    int loc = 0;
    for (int i = threadIdx.x; i < 8192; i += blockDim.x)
        if (m[i]) loc = 1;
    if (loc) atomicOr(&nz[threadIdx.x & 3], 1);
    __syncthreads();
    if (threadIdx.x == 0) {
        int mode;
        int tot = nz[0] | nz[1] | nz[2] | nz[3];
        if (!tot)                          mode = 0;
        else if (!(nz[1] | nz[2] | nz[3])) mode = 1; // int32 LE
        else if (!(nz[0] | nz[1]))         mode = 2; // float32 (0x3F800000)
        else                               mode = 0; // uint8/bool
        g_mask_mode = mode;
    }
}

// Convert mask (any dtype) into multiplicative float mask: 0 = masked, 1 = keep
__global__ void maskf_kernel(const void* __restrict__ m) {
    int i = blockIdx.x * blockDim.x + threadIdx.x;
    if (i >= BATCH * LKK) return;
    int mode = g_mask_mode;
    bool mm = (mode == 0) ? (((const unsigned char*)m)[i] != 0)
            : (mode == 1) ? (((const int*)m)[i] != 0)
                          : (((const float*)m)[i] != 0.f);
    g_maskf[i] = mm ? 0.f : 1.f;
}

// ---------------------------------------------------------------------------
// Weight transpose + fp16 convert: W[K][N] f32 -> WT[N][K] half.
// ---------------------------------------------------------------------------
__global__ void wtrans_kernel(const float* __restrict__ W, __half* __restrict__ WT) {
    __shared__ float t[32][33];
    int n0 = blockIdx.x * 32, k0 = blockIdx.y * 32;
    #pragma unroll
    for (int i = 0; i < 4; i++) {
        int k = threadIdx.y + i * 8;
        t[k][threadIdx.x] = W[(size_t)(k0 + k) * DMODEL + n0 + threadIdx.x];
    }
    __syncthreads();
    #pragma unroll
    for (int i = 0; i < 4; i++) {
        int n = threadIdx.y + i * 8;
        WT[(size_t)(n0 + n) * DMODEL + k0 + threadIdx.x] = __float2half(t[threadIdx.x][n]);
    }
}

// ---------------------------------------------------------------------------
// LayerNorm: one block per row of 1024, 256 threads. Output fp16.
// ---------------------------------------------------------------------------
__global__ void ln_kernel(const float* __restrict__ x,
                          const float* __restrict__ w,
                          const float* __restrict__ bia,
                          __half* __restrict__ out) {
    int row = blockIdx.x;
    int tid = threadIdx.x;
    const float4* xr = reinterpret_cast<const float4*>(x + (size_t)row * DMODEL);
    float4 a = xr[tid];
    float s  = a.x + a.y + a.z + a.w;
    float ss = a.x * a.x + a.y * a.y + a.z * a.z + a.w * a.w;

    __shared__ float rs[8], rss[8], stats[2];
    #pragma unroll
    for (int o = 16; o; o >>= 1) {
        s  += __shfl_xor_sync(0xffffffffu, s,  o);
        ss += __shfl_xor_sync(0xffffffffu, ss, o);
    }
    int wid = tid >> 5, lane = tid & 31;
    if (!lane) { rs[wid] = s; rss[wid] = ss; }
    __syncthreads();
    if (tid == 0) {
        float S = 0.f, SS = 0.f;
        #pragma unroll
        for (int i = 0; i < 8; i++) { S += rs[i]; SS += rss[i]; }
        float mean = S * (1.0f / DMODEL);
        float var  = SS * (1.0f / DMODEL) - mean * mean;
        stats[0] = mean;
        stats[1] = rsqrtf(var + 1e-5f);
    }
    __syncthreads();
    float mean = stats[0], rstd = stats[1];
    float4 wv = reinterpret_cast<const float4*>(w)[tid];
    float4 bv = reinterpret_cast<const float4*>(bia)[tid];
    __half2 h0 = __floats2half2_rn((a.x - mean) * rstd * wv.x + bv.x,
                                   (a.y - mean) * rstd * wv.y + bv.y);
    __half2 h1 = __floats2half2_rn((a.z - mean) * rstd * wv.z + bv.z,
                                   (a.w - mean) * rstd * wv.w + bv.w);
    __half2* orow = reinterpret_cast<__half2*>(out + (size_t)row * DMODEL);
    orow[tid * 2]     = h0;
    orow[tid * 2 + 1] = h1;
}

// ---------------------------------------------------------------------------
// fp16 tensor-core GEMM, cp.async 3-stage pipeline.
// C[M,N] = A[M,K] @ BT[N,K]^T. A half [M][K], BT half [N][K] (pre-transposed).
// 128x128x32 tiles, 256 threads, warp tile 64x32, m16n8k16.
// mode: 0 = half out, 1 = half transposed-per-head out (g_vt), 2 = float out.
// ---------------------------------------------------------------------------
#define TBM 128
#define TBN 128
#define TBK 32
#define KPAD 40                 // halves per smem row (20 words, conflict-free)
#define ASZH (TBM * KPAD)       // 5120 halves per stage per matrix

__global__ __launch_bounds__(256) void tgemm_kernel(
        const __half* __restrict__ A,
        const __half* __restrict__ BT,
        void* __restrict__ Cout,
        int M, int N, int K, int mode) {
    extern __shared__ __half gsm[];
    __half* As = gsm;              // 3 * ASZH
    __half* Bs = gsm + 3 * ASZH;   // 3 * ASZH

    int tid = threadIdx.x;
    int wid = tid >> 5, lane = tid & 31;
    int wm = wid >> 2, wn = wid & 3;                // 2 x 4 warp grid
    int m0 = blockIdx.y * TBM, n0 = blockIdx.x * TBN;
    int tg = lane & 3;

    float acc[4][4][4];
    #pragma unroll
    for (int i = 0; i < 4; i++)
        #pragma unroll
        for (int j = 0; j < 4; j++)
            #pragma unroll
            for (int t = 0; t < 4; t++) acc[i][j][t] = 0.f;

    auto load_tile = [&](int kt, int buf) {
        int k0 = kt * TBK;
        #pragma unroll
        for (int i = 0; i < 2; i++) {
            int cid = tid + i * 256;
            int row = cid >> 2, c8 = (cid & 3) * 8;
            cp_async16(&As[buf * ASZH + row * KPAD + c8],
                       A + (size_t)(m0 + row) * K + k0 + c8);
            cp_async16(&Bs[buf * ASZH + row * KPAD + c8],
                       BT + (size_t)(n0 + row) * K + k0 + c8);
        }
        cp_commit();
    };

    int arow = wm * 64 + (lane >> 2);
    int bn   = wn * 32 + (lane >> 2);

    int nt = K / TBK;
    load_tile(0, 0);
    load_tile(1, 1);

    for (int kt = 0; kt < nt; kt++) {
        int cur = kt % 3;
        if (kt + 2 < nt) cp_wait<1>(); else cp_wait<0>();
        __syncthreads();
        if (kt + 2 < nt) load_tile(kt + 2, (kt + 2) % 3);

        const unsigned* Aw = (const unsigned*)(As + cur * ASZH);
        const unsigned* Bw = (const unsigned*)(Bs + cur * ASZH);
        const int RS = KPAD / 2;  // 20 words per row

        #pragma unroll
        for (int ks = 0; ks < 2; ks++) {
            int kb2 = ks * 8;   // word offset of this k16 step
            unsigned af[4][4];
            #pragma unroll
            for (int mf = 0; mf < 4; mf++) {
                int r = arow + mf * 16;
                af[mf][0] = Aw[r * RS + kb2 + tg];
                af[mf][1] = Aw[(r + 8) * RS + kb2 + tg];
                af[mf][2] = Aw[r * RS + kb2 + 4 + tg];
                af[mf][3] = Aw[(r + 8) * RS + kb2 + 4 + tg];
            }
            unsigned bf[4][2];
            #pragma unroll
            for (int nf = 0; nf < 4; nf++) {
                bf[nf][0] = Bw[(bn + nf * 8) * RS + kb2 + tg];
                bf[nf][1] = Bw[(bn + nf * 8) * RS + kb2 + 4 + tg];
            }
            #pragma unroll
            for (int mf = 0; mf < 4; mf++)
                #pragma unroll
                for (int nf = 0; nf < 4; nf++)
                    mma_f16(acc[mf][nf], af[mf][0], af[mf][1], af[mf][2], af[mf][3],
                            bf[nf][0], bf[nf][1]);
        }
    }

    int crow = m0 + wm * 64 + (lane >> 2);
    int ccol = n0 + wn * 32 + tg * 2;
    #pragma unroll
    for (int mf = 0; mf < 4; mf++) {
        #pragma unroll
        for (int nf = 0; nf < 4; nf++) {
            int r = crow + mf * 16;
            int c = ccol + nf * 8;
            float v0 = acc[mf][nf][0], v1 = acc[mf][nf][1];
            float v2 = acc[mf][nf][2], v3 = acc[mf][nf][3];
            if (mode == 0) {
                __half* Ch = (__half*)Cout;
                *(__half2*)&Ch[(size_t)r * N + c]       = __floats2half2_rn(v0, v1);
                *(__half2*)&Ch[(size_t)(r + 8) * N + c] = __floats2half2_rn(v2, v3);
            } else if (mode == 2) {
                float* Cf = (float*)Cout;
                *(float2*)&Cf[(size_t)r * N + c]       = make_float2(v0, v1);
                *(float2*)&Cf[(size_t)(r + 8) * N + c] = make_float2(v2, v3);
            } else {
                // transposed-per-head store into g_vt[b][n][kv], n = h*64+d
                __half* vt = (__half*)Cout;
                int bb0 = r >> 11, kv0 = r & 2047;
                int bb1 = (r + 8) >> 11, kv1 = (r + 8) & 2047;
                vt[((size_t)(bb0 * 1024 + c)) * 2048 + kv0]     = __float2half(v0);
                vt[((size_t)(bb0 * 1024 + c + 1)) * 2048 + kv0] = __float2half(v1);
                vt[((size_t)(bb1 * 1024 + c)) * 2048 + kv1]     = __float2half(v2);
                vt[((size_t)(bb1 * 1024 + c + 1)) * 2048 + kv1] = __float2half(v3);
            }
        }
    }
}

// ---------------------------------------------------------------------------
// L2 norm over contiguous 64-half head vectors: one warp per vector.
// ---------------------------------------------------------------------------
__global__ void l2norm_kernel(__half* __restrict__ d, int nvec) {
    int idx  = blockIdx.x * blockDim.x + threadIdx.x;
    int warp = idx >> 5;
    int lane = idx & 31;
    if (warp >= nvec) return;
    __half2* p = reinterpret_cast<__half2*>(d) + (size_t)warp * 32 + lane;
    float2 f = __half22float2(*p);
    float ss = f.x * f.x + f.y * f.y;
    #pragma unroll
    for (int o = 16; o; o >>= 1) ss += __shfl_xor_sync(0xffffffffu, ss, o);
    float sc = 1.0f / fmaxf(sqrtf(ss), 1e-12f);
    *p = __floats2half2_rn(f.x * sc, f.y * sc);
}

// ---------------------------------------------------------------------------
// Flash attention, fp16 mma, fixed-max softmax, 256-row Q tile.
// Q[m][64] half, K[kv][64] half, Vt[d][kv] half (pre-transposed per head).
// Grid (LQ/256, H, B), 256 threads (8 warps: 4 row-slabs x 2 col-halves).
// Warp tile 64 q-rows x 32 k-cols.
// ---------------------------------------------------------------------------
#define QROWS 256
#define QP 72     // halves per smem row (36 words, conflict-free)
#define QPW 36

__global__ __launch_bounds__(256, 1) void attn_kernel(
        const __half* __restrict__ Q,
        const __half* __restrict__ Kp,
        const __half* __restrict__ Vt,
        const float* __restrict__ maskf,
        const float* __restrict__ tau_p,
        __half* __restrict__ O) {
    extern __shared__ __half smh[];
    __half* Qs = smh;                    // QROWS*QP
    __half* Ks = Qs + QROWS * QP;        // 2 * 64*QP
    __half* Vs = Ks + 2 * 64 * QP;       // 2 * 64*QP
    __half* Pb = Vs + 2 * 64 * QP;       // QROWS*QP
    float*  Ms = (float*)(Pb + QROWS * QP);  // 2 * 64
    float*  lpart = Ms + 128;                // 2 * QROWS

    int tid  = threadIdx.x;
    int wid  = tid >> 5, lane = tid & 31;
    int wm   = wid >> 1;          // 0..3 : 64-row slab
    int wn   = wid & 1;           // 0..1 : 32-col half
    int q0   = blockIdx.x * QROWS;
    int h    = blockIdx.y;
    int b    = blockIdx.z;
    int tg   = lane & 3;

    float inv_tau = 1.0f / (*tau_p + 1e-6f);
    float MFIX = fabsf(inv_tau);   // scores bounded by |1/tau| (unit q,k)

    const __half* Qbase = Q  + ((size_t)(b * LQQ + q0)) * DMODEL + h * DHEAD;
    const __half* Kbase = Kp + ((size_t)b * LKK) * DMODEL + h * DHEAD;
    const __half* Vbase = Vt + ((size_t)(b * 1024 + h * DHEAD)) * 2048;  // rows = d
    const float*  Mbase = maskf + (size_t)b * LKK;

    // Q tile: 256 rows x 64 halves = 2048 16B-chunks, 8 per thread
    #pragma unroll
    for (int i = 0; i < 8; i++) {
        int cid = tid + i * 256;
        int r = cid >> 3, c8 = (cid & 7) * 8;
        cp_async16(&Qs[r * QP + c8], Qbase + (size_t)r * DMODEL + c8);
    }
    cp_commit();

    auto load_kv = [&](int k0, int buf) {
        #pragma unroll
        for (int i = 0; i < 2; i++) {
            int cid = tid + i * 256;
            int r = cid >> 3, c8 = (cid & 7) * 8;
            cp_async16(&Ks[buf * 64 * QP + r * QP + c8],
                       Kbase + (size_t)(k0 + r) * DMODEL + c8);
            cp_async16(&Vs[buf * 64 * QP + r * QP + c8],
                       Vbase + (size_t)r * 2048 + k0 + c8);
        }
        if (tid < 16) cp_async16(&Ms[buf * 64 + tid * 4], Mbase + k0 + tid * 4);
        cp_commit();
    };

    load_kv(0, 0);

    float oacc[4][4][4];
    #pragma unroll
    for (int m = 0; m < 4; m++)
        #pragma unroll
        for (int i = 0; i < 4; i++)
            #pragma unroll
            for (int j = 0; j < 4; j++) oacc[m][i][j] = 0.f;
    float lsum[4][2] = {};

    int rA = wm * 64 + (lane >> 2);   // base A-frag row (mf adds 16)
    int nB = wn * 32 + (lane >> 2);   // B-frag n
    int scb = wn * 32 + tg * 2;

    const unsigned* Qw = (const unsigned*)Qs;
    const unsigned* Pw = (const unsigned*)Pb;

    const int NT = LKK / 64;
    for (int kt = 0; kt < NT; kt++) {
        int cur = kt & 1;
        cp_wait<0>();
        __syncthreads();
        if (kt + 1 < NT) load_kv((kt + 1) * 64, cur ^ 1);

        const unsigned* Kw = (const unsigned*)(Ks + cur * 64 * QP);
        const unsigned* Vw = (const unsigned*)(Vs + cur * 64 * QP);
        const float*    Msb = Ms + cur * 64;

        // S = Q . K^T  (per warp: 64 rows x 32 cols), k = 64 halves = 4 k16 steps
        float sacc[4][4][4];
        #pragma unroll
        for (int m = 0; m < 4; m++)
            #pragma unroll
            for (int i = 0; i < 4; i++)
                #pragma unroll
                for (int j = 0; j < 4; j++) sacc[m][i][j] = 0.f;

        #pragma unroll
        for (int ks = 0; ks < 4; ks++) {
            int kb2 = ks * 8;
            unsigned bf[4][2];
            #pragma unroll
            for (int nf = 0; nf < 4; nf++) {
                bf[nf][0] = Kw[(nB + nf * 8) * QPW + kb2 + tg];
                bf[nf][1] = Kw[(nB + nf * 8) * QPW + kb2 + 4 + tg];
            }
            #pragma unroll
            for (int mf = 0; mf < 4; mf++) {
                int r = rA + mf * 16;
                unsigned a0 = Qw[r * QPW + kb2 + tg];
                unsigned a1 = Qw[(r + 8) * QPW + kb2 + tg];
                unsigned a2 = Qw[r * QPW + kb2 + 4 + tg];
                unsigned a3 = Qw[(r + 8) * QPW + kb2 + 4 + tg];
                #pragma unroll
                for (int nf = 0; nf < 4; nf++)
                    mma_f16(sacc[mf][nf], a0, a1, a2, a3, bf[nf][0], bf[nf][1]);
            }
        }

        // exp (fixed max) + mask, accumulate row sums, write P (fp16) to smem
        #pragma unroll
        for (int mf = 0; mf < 4; mf++) {
            int sr = rA + mf * 16;
            #pragma unroll
            for (int nf = 0; nf < 4; nf++) {
                int c = scb + nf * 8;
                float mk0 = Msb[c], mk1 = Msb[c + 1];
                float p00 = __expf(fminf(sacc[mf][nf][0] * inv_tau - MFIX, 0.f)) * mk0;
                float p01 = __expf(fminf(sacc[mf][nf][1] * inv_tau - MFIX, 0.f)) * mk1;
                float p10 = __expf(fminf(sacc[mf][nf][2] * inv_tau - MFIX, 0.f)) * mk0;
                float p11 = __expf(fminf(sacc[mf][nf][3] * inv_tau - MFIX, 0.f)) * mk1;
                lsum[mf][0] += p00 + p01;
                lsum[mf][1] += p10 + p11;
                *(__half2*)&Pb[sr * QP + c]       = __floats2half2_rn(p00, p01);
                *(__half2*)&Pb[(sr + 8) * QP + c] = __floats2half2_rn(p10, p11);
            }
        }
        __syncthreads();   // Pb complete before PV mma

        // O += P . V   (A = P[m][kv], B = Vt[d][kv])
        #pragma unroll
        for (int ks = 0; ks < 4; ks++) {
            int kb2 = ks * 8;
            unsigned bf[4][2];
            #pragma unroll
            for (int nf = 0; nf < 4; nf++) {
                bf[nf][0] = Vw[(nB + nf * 8) * QPW + kb2 + tg];
                bf[nf][1] = Vw[(nB + nf * 8) * QPW + kb2 + 4 + tg];
            }
            #pragma unroll
            for (int mf = 0; mf < 4; mf++) {
                int r = rA + mf * 16;
                unsigned a0 = Pw[r * QPW + kb2 + tg];
                unsigned a1 = Pw[(r + 8) * QPW + kb2 + tg];
                unsigned a2 = Pw[r * QPW + kb2 + 4 + tg];
                unsigned a3 = Pw[(r + 8) * QPW + kb2 + 4 + tg];
                #pragma unroll
                for (int nf = 0; nf < 4; nf++)
                    mma_f16(oacc[mf][nf], a0, a1, a2, a3, bf[nf][0], bf[nf][1]);
            }
        }
    }

    // combine row sums: quad-reduce then across the two wn halves via smem
    #pragma unroll
    for (int mf = 0; mf < 4; mf++) {
        lsum[mf][0] += __shfl_xor_sync(0xffffffffu, lsum[mf][0], 1);
        lsum[mf][0] += __shfl_xor_sync(0xffffffffu, lsum[mf][0], 2);
        lsum[mf][1] += __shfl_xor_sync(0xffffffffu, lsum[mf][1], 1);
        lsum[mf][1] += __shfl_xor_sync(0xffffffffu, lsum[mf][1], 2);
    }
    __syncthreads();
    if (tg == 0) {
        #pragma unroll
        for (int mf = 0; mf < 4; mf++) {
            int r = rA + mf * 16;
            lpart[wn * QROWS + r]     = lsum[mf][0];
            lpart[wn * QROWS + r + 8] = lsum[mf][1];
        }
    }
    __syncthreads();

    // Epilogue: divide by l, store fp16 (feeds final GEMM)
    #pragma unroll
    for (int mf = 0; mf < 4; mf++) {
        int r0 = rA + mf * 16;
        float li0 = 1.0f / (lpart[r0]     + lpart[QROWS + r0]);
        float li1 = 1.0f / (lpart[r0 + 8] + lpart[QROWS + r0 + 8]);
        int gcol = h * DHEAD + wn * 32 + tg * 2;
        #pragma unroll
        for (int nf = 0; nf < 4; nf++) {
            size_t base0 = ((size_t)(b * LQQ + q0 + r0)) * DMODEL + gcol + nf * 8;
            size_t base1 = ((size_t)(b * LQQ + q0 + r0 + 8)) * DMODEL + gcol + nf * 8;
            *(__half2*)&O[base0] = __floats2half2_rn(oacc[mf][nf][0] * li0,
                                                     oacc[mf][nf][1] * li0);
            *(__half2*)&O[base1] = __floats2half2_rn(oacc[mf][nf][2] * li1,
                                                     oacc[mf][nf][3] * li1);
        }
    }
}

// ---------------------------------------------------------------------------
// Launcher
// ---------------------------------------------------------------------------
extern "C" void kernel_launch(void* const* d_in, const int* in_sizes, int n_in,
                              void* d_out, int out_size) {
    const float* x     = (const float*)d_in[0];
    const float* ctx   = (const float*)d_in[1];
    const void*  mask  = d_in[2];
    const float* lnqw  = (const float*)d_in[3];
    const float* lnqb  = (const float*)d_in[4];
    const float* lncw  = (const float*)d_in[5];
    const float* lncb  = (const float*)d_in[6];
    const float* Wq    = (const float*)d_in[7];
    const float* Wk    = (const float*)d_in[8];
    const float* Wv    = (const float*)d_in[9];
    const float* Wo    = (const float*)d_in[10];
    const float* taup  = (const float*)d_in[11];
    float* out = (float*)d_out;

    __half *qln, *kvln, *q, *k, *vt, *ao, *wq, *wk, *wv, *wo;
    float *maskf;
    cudaGetSymbolAddress((void**)&qln,   g_qln);
    cudaGetSymbolAddress((void**)&kvln,  g_kvln);
    cudaGetSymbolAddress((void**)&q,     g_q);
    cudaGetSymbolAddress((void**)&k,     g_k);
    cudaGetSymbolAddress((void**)&vt,    g_vt);
    cudaGetSymbolAddress((void**)&ao,    g_ao);
    cudaGetSymbolAddress((void**)&maskf, g_maskf);
    cudaGetSymbolAddress((void**)&wq,    g_wq);
    cudaGetSymbolAddress((void**)&wk,    g_wk);
    cudaGetSymbolAddress((void**)&wv,    g_wv);
    cudaGetSymbolAddress((void**)&wo,    g_wo);

    // GEMM dynamic smem (3-stage, halves)
    const int smem_gemm = (int)(6 * ASZH * sizeof(__half));
    cudaFuncSetAttribute(tgemm_kernel, cudaFuncAttributeMaxDynamicSharedMemorySize, smem_gemm);

    // attention dynamic smem
    const int smem_attn = (int)((QROWS * QP + 2 * 64 * QP + 2 * 64 * QP + QROWS * QP)
                                    * sizeof(__half)
                              + (128 + 2 * QROWS) * sizeof(float));
    cudaFuncSetAttribute(attn_kernel, cudaFuncAttributeMaxDynamicSharedMemorySize, smem_attn);

    detect_mask_kernel<<<1, 256>>>((const unsigned char*)mask);
    maskf_kernel<<<(BATCH * LKK + 255) / 256, 256>>>(mask);

    // transpose + fp16-convert weights
    dim3 wtb(32, 8), wtg(DMODEL / 32, DMODEL / 32);
    wtrans_kernel<<<wtg, wtb>>>(Wq, wq);
    wtrans_kernel<<<wtg, wtb>>>(Wk, wk);
    wtrans_kernel<<<wtg, wtb>>>(Wv, wv);
    wtrans_kernel<<<wtg, wtb>>>(Wo, wo);

    ln_kernel<<<BATCH * LQQ, 256>>>(x,   lnqw, lnqb, qln);
    ln_kernel<<<BATCH * LKK, 256>>>(ctx, lncw, lncb, kvln);

    dim3 gg(DMODEL / TBN, (BATCH * LQQ) / TBM);
    tgemm_kernel<<<gg, 256, smem_gemm>>>(qln,  wq, q,  BATCH * LQQ, DMODEL, DMODEL, 0);
    tgemm_kernel<<<gg, 256, smem_gemm>>>(kvln, wk, k,  BATCH * LKK, DMODEL, DMODEL, 0);
    tgemm_kernel<<<gg, 256, smem_gemm>>>(kvln, wv, vt, BATCH * LKK, DMODEL, DMODEL, 1);

    int nvec = BATCH * LQQ * NHEAD;
    l2norm_kernel<<<(nvec * 32) / 256, 256>>>(q, nvec);
    l2norm_kernel<<<(nvec * 32) / 256, 256>>>(k, nvec);

    attn_kernel<<<dim3(LQQ / QROWS, NHEAD, BATCH), 256, smem_attn>>>(q, k, vt, maskf, taup, ao);

    tgemm_kernel<<<gg, 256, smem_gemm>>>(ao, wo, out, BATCH * LQQ, DMODEL, DMODEL, 2);
}

// round 7
// speedup vs baseline: 6.2870x; 1.0686x over previous
#include <cuda_runtime.h>
#include <cuda_fp16.h>
#include <math.h>

// Problem constants
#define BATCH 4
#define LQQ   2048
#define LKK   2048
#define DMODEL 1024
#define NHEAD 16
#define DHEAD 64

// Scratch (static device arrays -- no runtime allocation allowed)
__device__ __half g_qln [BATCH * LQQ * DMODEL];
__device__ __half g_kvln[BATCH * LKK * DMODEL];
__device__ __half g_q   [BATCH * LQQ * DMODEL];
__device__ __half g_k   [BATCH * LKK * DMODEL];
__device__ __half g_vt  [BATCH * NHEAD * DHEAD * LKK];  // [b][h][d][kv]
__device__ __half g_ao  [BATCH * LQQ * DMODEL];
__device__ __half g_wq  [DMODEL * DMODEL];  // transposed [N][K]
__device__ __half g_wk  [DMODEL * DMODEL];
__device__ __half g_wv  [DMODEL * DMODEL];
__device__ __half g_wo  [DMODEL * DMODEL];
__device__ float  g_maskf[BATCH * LKK];   // 0.0 = masked, 1.0 = keep
__device__ int    g_mask_mode;            // 0=uint8, 1=int32, 2=float32

// ---------------------------------------------------------------------------
// mma / cp.async / ldmatrix helpers
// ---------------------------------------------------------------------------
__device__ __forceinline__ void mma_f16(float c[4],
                                        unsigned a0, unsigned a1, unsigned a2, unsigned a3,
                                        unsigned b0, unsigned b1) {
    asm volatile(
        "mma.sync.aligned.m16n8k16.row.col.f32.f16.f16.f32 "
        "{%0,%1,%2,%3},{%4,%5,%6,%7},{%8,%9},{%0,%1,%2,%3};"
        : "+f"(c[0]), "+f"(c[1]), "+f"(c[2]), "+f"(c[3])
        : "r"(a0), "r"(a1), "r"(a2), "r"(a3), "r"(b0), "r"(b1));
}

__device__ __forceinline__ void cp_async16(void* smem_dst, const void* gmem_src) {
    unsigned sa = (unsigned)__cvta_generic_to_shared(smem_dst);
    asm volatile("cp.async.cg.shared.global [%0], [%1], 16;" :: "r"(sa), "l"(gmem_src));
}
__device__ __forceinline__ void cp_commit() {
    asm volatile("cp.async.commit_group;");
}
template <int N>
__device__ __forceinline__ void cp_wait() {
    asm volatile("cp.async.wait_group %0;" :: "n"(N));
}

__device__ __forceinline__ unsigned smem_u32(const void* p) {
    return (unsigned)__cvta_generic_to_shared(p);
}
__device__ __forceinline__ void ldsm4(unsigned& d0, unsigned& d1,
                                      unsigned& d2, unsigned& d3, unsigned saddr) {
    asm volatile("ldmatrix.sync.aligned.m8n8.x4.shared.b16 {%0,%1,%2,%3}, [%4];"
                 : "=r"(d0), "=r"(d1), "=r"(d2), "=r"(d3) : "r"(saddr));
}

// ---------------------------------------------------------------------------
// Mask dtype detection (bool array may arrive as u8/i32/f32)
// ---------------------------------------------------------------------------
__global__ void detect_mask_kernel(const unsigned char* __restrict__ m) {
    __shared__ int nz[4];
    if (threadIdx.x < 4) nz[threadIdx.x] = 0;
    __syncthreads();
    int loc = 0;
    for (int i = threadIdx.x; i < 8192; i += blockDim.x)
        if (m[i]) loc = 1;
    if (loc) atomicOr(&nz[threadIdx.x & 3], 1);
    __syncthreads();
    if (threadIdx.x == 0) {
        int mode;
        int tot = nz[0] | nz[1] | nz[2] | nz[3];
        if (!tot)                          mode = 0;
        else if (!(nz[1] | nz[2] | nz[3])) mode = 1; // int32 LE
        else if (!(nz[0] | nz[1]))         mode = 2; // float32 (0x3F800000)
        else                               mode = 0; // uint8/bool
        g_mask_mode = mode;
    }
}

// Convert mask (any dtype) into multiplicative float mask: 0 = masked, 1 = keep
__global__ void maskf_kernel(const void* __restrict__ m) {
    int i = blockIdx.x * blockDim.x + threadIdx.x;
    if (i >= BATCH * LKK) return;
    int mode = g_mask_mode;
    bool mm = (mode == 0) ? (((const unsigned char*)m)[i] != 0)
            : (mode == 1) ? (((const int*)m)[i] != 0)
                          : (((const float*)m)[i] != 0.f);
    g_maskf[i] = mm ? 0.f : 1.f;
}

// ---------------------------------------------------------------------------
// Weight transpose + fp16 convert: W[K][N] f32 -> WT[N][K] half.
// ---------------------------------------------------------------------------
__global__ void wtrans_kernel(const float* __restrict__ W, __half* __restrict__ WT) {
    __shared__ float t[32][33];
    int n0 = blockIdx.x * 32, k0 = blockIdx.y * 32;
    #pragma unroll
    for (int i = 0; i < 4; i++) {
        int k = threadIdx.y + i * 8;
        t[k][threadIdx.x] = W[(size_t)(k0 + k) * DMODEL + n0 + threadIdx.x];
    }
    __syncthreads();
    #pragma unroll
    for (int i = 0; i < 4; i++) {
        int n = threadIdx.y + i * 8;
        WT[(size_t)(n0 + n) * DMODEL + k0 + threadIdx.x] = __float2half(t[threadIdx.x][n]);
    }
}

// ---------------------------------------------------------------------------
// LayerNorm: one block per row of 1024, 256 threads. Output fp16.
// ---------------------------------------------------------------------------
__global__ void ln_kernel(const float* __restrict__ x,
                          const float* __restrict__ w,
                          const float* __restrict__ bia,
                          __half* __restrict__ out) {
    int row = blockIdx.x;
    int tid = threadIdx.x;
    const float4* xr = reinterpret_cast<const float4*>(x + (size_t)row * DMODEL);
    float4 a = xr[tid];
    float s  = a.x + a.y + a.z + a.w;
    float ss = a.x * a.x + a.y * a.y + a.z * a.z + a.w * a.w;

    __shared__ float rs[8], rss[8], stats[2];
    #pragma unroll
    for (int o = 16; o; o >>= 1) {
        s  += __shfl_xor_sync(0xffffffffu, s,  o);
        ss += __shfl_xor_sync(0xffffffffu, ss, o);
    }
    int wid = tid >> 5, lane = tid & 31;
    if (!lane) { rs[wid] = s; rss[wid] = ss; }
    __syncthreads();
    if (tid == 0) {
        float S = 0.f, SS = 0.f;
        #pragma unroll
        for (int i = 0; i < 8; i++) { S += rs[i]; SS += rss[i]; }
        float mean = S * (1.0f / DMODEL);
        float var  = SS * (1.0f / DMODEL) - mean * mean;
        stats[0] = mean;
        stats[1] = rsqrtf(var + 1e-5f);
    }
    __syncthreads();
    float mean = stats[0], rstd = stats[1];
    float4 wv = reinterpret_cast<const float4*>(w)[tid];
    float4 bv = reinterpret_cast<const float4*>(bia)[tid];
    __half2 h0 = __floats2half2_rn((a.x - mean) * rstd * wv.x + bv.x,
                                   (a.y - mean) * rstd * wv.y + bv.y);
    __half2 h1 = __floats2half2_rn((a.z - mean) * rstd * wv.z + bv.z,
                                   (a.w - mean) * rstd * wv.w + bv.w);
    __half2* orow = reinterpret_cast<__half2*>(out + (size_t)row * DMODEL);
    orow[tid * 2]     = h0;
    orow[tid * 2 + 1] = h1;
}

// ---------------------------------------------------------------------------
// fp16 tensor-core GEMM, cp.async 3-stage pipeline, ldmatrix fragment loads.
// C[M,N] = A[M,K] @ BT[N,K]^T. 128x128x32 tiles, 256 threads, warp 64x32.
// mode: 0 = half out, 1 = half transposed-per-head out (g_vt), 2 = float out.
// ---------------------------------------------------------------------------
#define TBM 128
#define TBN 128
#define TBK 32
#define KPAD 40                 // halves per smem row
#define ROWB (KPAD * 2)         // 80 bytes per row
#define ASZH (TBM * KPAD)       // halves per stage per matrix
#define STAGEB (ASZH * 2)       // bytes per stage

__global__ __launch_bounds__(256) void tgemm_kernel(
        const __half* __restrict__ A,
        const __half* __restrict__ BT,
        void* __restrict__ Cout,
        int M, int N, int K, int mode) {
    extern __shared__ __half gsm[];
    __half* As = gsm;              // 3 * ASZH
    __half* Bs = gsm + 3 * ASZH;   // 3 * ASZH

    int tid = threadIdx.x;
    int wid = tid >> 5, lane = tid & 31;
    int wm = wid >> 2, wn = wid & 3;                // 2 x 4 warp grid
    int m0 = blockIdx.y * TBM, n0 = blockIdx.x * TBN;
    int tg = lane & 3;
    int lm = lane >> 3;   // ldmatrix matrix id 0..3
    int lr = lane & 7;    // row within 8x8 matrix

    float acc[4][4][4];
    #pragma unroll
    for (int i = 0; i < 4; i++)
        #pragma unroll
        for (int j = 0; j < 4; j++)
            #pragma unroll
            for (int t = 0; t < 4; t++) acc[i][j][t] = 0.f;

    auto load_tile = [&](int kt, int buf) {
        int k0 = kt * TBK;
        #pragma unroll
        for (int i = 0; i < 2; i++) {
            int cid = tid + i * 256;
            int row = cid >> 2, c8 = (cid & 3) * 8;
            cp_async16(&As[buf * ASZH + row * KPAD + c8],
                       A + (size_t)(m0 + row) * K + k0 + c8);
            cp_async16(&Bs[buf * ASZH + row * KPAD + c8],
                       BT + (size_t)(n0 + row) * K + k0 + c8);
        }
        cp_commit();
    };

    // per-lane ldmatrix base byte offsets (within a stage)
    // A: matrices (a0,a1,a2,a3) = (r0..7,k0-7),(r8..15,k0-7),(r0..7,k8-15),(r8..15,k8-15)
    unsigned aoff = (unsigned)((wm * 64 + (lm & 1) * 8 + lr) * ROWB + (lm >> 1) * 16);
    // B: group g covers n-frags 2g,2g+1: matrices (nf2g,b0),(nf2g,b1),(nf2g+1,b0),(nf2g+1,b1)
    unsigned boff = (unsigned)((wn * 32 + (lm >> 1) * 8 + lr) * ROWB + (lm & 1) * 16);

    unsigned aBase = smem_u32(As) + aoff;
    unsigned bBase = smem_u32(Bs) + boff;

    int nt = K / TBK;
    load_tile(0, 0);
    load_tile(1, 1);

    for (int kt = 0; kt < nt; kt++) {
        int cur = kt % 3;
        if (kt + 2 < nt) cp_wait<1>(); else cp_wait<0>();
        __syncthreads();
        if (kt + 2 < nt) load_tile(kt + 2, (kt + 2) % 3);

        unsigned aS = aBase + cur * STAGEB;
        unsigned bS = bBase + cur * STAGEB;

        #pragma unroll
        for (int ks = 0; ks < 2; ks++) {
            unsigned kofs = ks * 32;   // 8 words = 32 bytes per k16 step
            unsigned af[4][4];
            #pragma unroll
            for (int mf = 0; mf < 4; mf++)
                ldsm4(af[mf][0], af[mf][1], af[mf][2], af[mf][3],
                      aS + kofs + mf * 16 * ROWB);
            unsigned bf[4][2];
            #pragma unroll
            for (int g = 0; g < 2; g++)
                ldsm4(bf[g*2][0], bf[g*2][1], bf[g*2+1][0], bf[g*2+1][1],
                      bS + kofs + g * 16 * ROWB);
            #pragma unroll
            for (int mf = 0; mf < 4; mf++)
                #pragma unroll
                for (int nf = 0; nf < 4; nf++)
                    mma_f16(acc[mf][nf], af[mf][0], af[mf][1], af[mf][2], af[mf][3],
                            bf[nf][0], bf[nf][1]);
        }
    }

    int crow = m0 + wm * 64 + (lane >> 2);
    int ccol = n0 + wn * 32 + tg * 2;
    #pragma unroll
    for (int mf = 0; mf < 4; mf++) {
        #pragma unroll
        for (int nf = 0; nf < 4; nf++) {
            int r = crow + mf * 16;
            int c = ccol + nf * 8;
            float v0 = acc[mf][nf][0], v1 = acc[mf][nf][1];
            float v2 = acc[mf][nf][2], v3 = acc[mf][nf][3];
            if (mode == 0) {
                __half* Ch = (__half*)Cout;
                *(__half2*)&Ch[(size_t)r * N + c]       = __floats2half2_rn(v0, v1);
                *(__half2*)&Ch[(size_t)(r + 8) * N + c] = __floats2half2_rn(v2, v3);
            } else if (mode == 2) {
                float* Cf = (float*)Cout;
                *(float2*)&Cf[(size_t)r * N + c]       = make_float2(v0, v1);
                *(float2*)&Cf[(size_t)(r + 8) * N + c] = make_float2(v2, v3);
            } else {
                // transposed-per-head store into g_vt[b][n][kv], n = h*64+d
                __half* vt = (__half*)Cout;
                int bb0 = r >> 11, kv0 = r & 2047;
                int bb1 = (r + 8) >> 11, kv1 = (r + 8) & 2047;
                vt[((size_t)(bb0 * 1024 + c)) * 2048 + kv0]     = __float2half(v0);
                vt[((size_t)(bb0 * 1024 + c + 1)) * 2048 + kv0] = __float2half(v1);
                vt[((size_t)(bb1 * 1024 + c)) * 2048 + kv1]     = __float2half(v2);
                vt[((size_t)(bb1 * 1024 + c + 1)) * 2048 + kv1] = __float2half(v3);
            }
        }
    }
}

// ---------------------------------------------------------------------------
// L2 norm over contiguous 64-half head vectors: one warp per vector.
// ---------------------------------------------------------------------------
__global__ void l2norm_kernel(__half* __restrict__ d, int nvec) {
    int idx  = blockIdx.x * blockDim.x + threadIdx.x;
    int warp = idx >> 5;
    int lane = idx & 31;
    if (warp >= nvec) return;
    __half2* p = reinterpret_cast<__half2*>(d) + (size_t)warp * 32 + lane;
    float2 f = __half22float2(*p);
    float ss = f.x * f.x + f.y * f.y;
    #pragma unroll
    for (int o = 16; o; o >>= 1) ss += __shfl_xor_sync(0xffffffffu, ss, o);
    float sc = 1.0f / fmaxf(sqrtf(ss), 1e-12f);
    *p = __floats2half2_rn(f.x * sc, f.y * sc);
}

// ---------------------------------------------------------------------------
// Flash attention, fp16 mma + ldmatrix, fixed-max softmax, 256-row Q tile.
// Q[m][64] half, K[kv][64] half, Vt[d][kv] half (pre-transposed per head).
// Grid (LQ/256, H, B), 256 threads (8 warps: 4 row-slabs x 2 col-halves).
// ---------------------------------------------------------------------------
#define QROWS 256
#define QP 72       // halves per smem row
#define QROWB (QP * 2)   // 144 bytes

__global__ __launch_bounds__(256, 1) void attn_kernel(
        const __half* __restrict__ Q,
        const __half* __restrict__ Kp,
        const __half* __restrict__ Vt,
        const float* __restrict__ maskf,
        const float* __restrict__ tau_p,
        __half* __restrict__ O) {
    extern __shared__ __half smh[];
    __half* Qs = smh;                    // QROWS*QP
    __half* Ks = Qs + QROWS * QP;        // 2 * 64*QP
    __half* Vs = Ks + 2 * 64 * QP;       // 2 * 64*QP
    __half* Pb = Vs + 2 * 64 * QP;       // QROWS*QP
    float*  Ms = (float*)(Pb + QROWS * QP);  // 2 * 64
    float*  lpart = Ms + 128;                // 2 * QROWS

    int tid  = threadIdx.x;
    int wid  = tid >> 5, lane = tid & 31;
    int wm   = wid >> 1;          // 0..3 : 64-row slab
    int wn   = wid & 1;           // 0..1 : 32-col half
    int q0   = blockIdx.x * QROWS;
    int h    = blockIdx.y;
    int b    = blockIdx.z;
    int tg   = lane & 3;
    int lm   = lane >> 3;
    int lr   = lane & 7;

    float inv_tau = 1.0f / (*tau_p + 1e-6f);
    float MFIX = fabsf(inv_tau);   // scores bounded by |1/tau| (unit q,k)

    const __half* Qbase = Q  + ((size_t)(b * LQQ + q0)) * DMODEL + h * DHEAD;
    const __half* Kbase = Kp + ((size_t)b * LKK) * DMODEL + h * DHEAD;
    const __half* Vbase = Vt + ((size_t)(b * 1024 + h * DHEAD)) * 2048;  // rows = d
    const float*  Mbase = maskf + (size_t)b * LKK;

    // Q tile: 256 rows x 64 halves = 2048 16B-chunks, 8 per thread
    #pragma unroll
    for (int i = 0; i < 8; i++) {
        int cid = tid + i * 256;
        int r = cid >> 3, c8 = (cid & 7) * 8;
        cp_async16(&Qs[r * QP + c8], Qbase + (size_t)r * DMODEL + c8);
    }
    cp_commit();

    auto load_kv = [&](int k0, int buf) {
        #pragma unroll
        for (int i = 0; i < 2; i++) {
            int cid = tid + i * 256;
            int r = cid >> 3, c8 = (cid & 7) * 8;
            cp_async16(&Ks[buf * 64 * QP + r * QP + c8],
                       Kbase + (size_t)(k0 + r) * DMODEL + c8);
            cp_async16(&Vs[buf * 64 * QP + r * QP + c8],
                       Vbase + (size_t)r * 2048 + k0 + c8);
        }
        if (tid < 16) cp_async16(&Ms[buf * 64 + tid * 4], Mbase + k0 + tid * 4);
        cp_commit();
    };

    load_kv(0, 0);

    float oacc[4][4][4];
    #pragma unroll
    for (int m = 0; m < 4; m++)
        #pragma unroll
        for (int i = 0; i < 4; i++)
            #pragma unroll
            for (int j = 0; j < 4; j++) oacc[m][i][j] = 0.f;
    float lsum[4][2] = {};

    int rA = wm * 64 + (lane >> 2);   // S/epilogue row base
    int scb = wn * 32 + tg * 2;

    // ldmatrix lane base offsets
    unsigned aoff = (unsigned)((wm * 64 + (lm & 1) * 8 + lr) * QROWB + (lm >> 1) * 16);
    unsigned boff = (unsigned)((wn * 32 + (lm >> 1) * 8 + lr) * QROWB + (lm & 1) * 16);
    unsigned qA = smem_u32(Qs) + aoff;
    unsigned pA = smem_u32(Pb) + aoff;
    unsigned kB = smem_u32(Ks) + boff;
    unsigned vB = smem_u32(Vs) + boff;
    const unsigned KVSTAGE = 64 * QP * 2;  // bytes per KV buffer

    const int NT = LKK / 64;
    for (int kt = 0; kt < NT; kt++) {
        int cur = kt & 1;
        cp_wait<0>();
        __syncthreads();
        if (kt + 1 < NT) load_kv((kt + 1) * 64, cur ^ 1);

        unsigned kS = kB + cur * KVSTAGE;
        unsigned vS = vB + cur * KVSTAGE;
        const float* Msb = Ms + cur * 64;

        // S = Q . K^T  (per warp: 64 rows x 32 cols), 4 k16 steps
        float sacc[4][4][4];
        #pragma unroll
        for (int m = 0; m < 4; m++)
            #pragma unroll
            for (int i = 0; i < 4; i++)
                #pragma unroll
                for (int j = 0; j < 4; j++) sacc[m][i][j] = 0.f;

        #pragma unroll
        for (int ks = 0; ks < 4; ks++) {
            unsigned kofs = ks * 32;
            unsigned bf[4][2];
            #pragma unroll
            for (int g = 0; g < 2; g++)
                ldsm4(bf[g*2][0], bf[g*2][1], bf[g*2+1][0], bf[g*2+1][1],
                      kS + kofs + g * 16 * QROWB);
            #pragma unroll
            for (int mf = 0; mf < 4; mf++) {
                unsigned a0, a1, a2, a3;
                ldsm4(a0, a1, a2, a3, qA + kofs + mf * 16 * QROWB);
                #pragma unroll
                for (int nf = 0; nf < 4; nf++)
                    mma_f16(sacc[mf][nf], a0, a1, a2, a3, bf[nf][0], bf[nf][1]);
            }
        }

        // exp (fixed max) + mask, accumulate row sums, write P (fp16) to smem
        #pragma unroll
        for (int mf = 0; mf < 4; mf++) {
            int sr = rA + mf * 16;
            #pragma unroll
            for (int nf = 0; nf < 4; nf++) {
                int c = scb + nf * 8;
                float mk0 = Msb[c], mk1 = Msb[c + 1];
                float p00 = __expf(fminf(sacc[mf][nf][0] * inv_tau - MFIX, 0.f)) * mk0;
                float p01 = __expf(fminf(sacc[mf][nf][1] * inv_tau - MFIX, 0.f)) * mk1;
                float p10 = __expf(fminf(sacc[mf][nf][2] * inv_tau - MFIX, 0.f)) * mk0;
                float p11 = __expf(fminf(sacc[mf][nf][3] * inv_tau - MFIX, 0.f)) * mk1;
                lsum[mf][0] += p00 + p01;
                lsum[mf][1] += p10 + p11;
                *(__half2*)&Pb[sr * QP + c]       = __floats2half2_rn(p00, p01);
                *(__half2*)&Pb[(sr + 8) * QP + c] = __floats2half2_rn(p10, p11);
            }
        }
        __syncthreads();   // Pb complete before PV mma

        // O += P . V   (A = P[m][kv], B = Vt[d][kv])
        #pragma unroll
        for (int ks = 0; ks < 4; ks++) {
            unsigned kofs = ks * 32;
            unsigned bf[4][2];
            #pragma unroll
            for (int g = 0; g < 2; g++)
                ldsm4(bf[g*2][0], bf[g*2][1], bf[g*2+1][0], bf[g*2+1][1],
                      vS + kofs + g * 16 * QROWB);
            #pragma unroll
            for (int mf = 0; mf < 4; mf++) {
                unsigned a0, a1, a2, a3;
                ldsm4(a0, a1, a2, a3, pA + kofs + mf * 16 * QROWB);
                #pragma unroll
                for (int nf = 0; nf < 4; nf++)
                    mma_f16(oacc[mf][nf], a0, a1, a2, a3, bf[nf][0], bf[nf][1]);
            }
        }
    }

    // combine row sums: quad-reduce then across the two wn halves via smem
    #pragma unroll
    for (int mf = 0; mf < 4; mf++) {
        lsum[mf][0] += __shfl_xor_sync(0xffffffffu, lsum[mf][0], 1);
        lsum[mf][0] += __shfl_xor_sync(0xffffffffu, lsum[mf][0], 2);
        lsum[mf][1] += __shfl_xor_sync(0xffffffffu, lsum[mf][1], 1);
        lsum[mf][1] += __shfl_xor_sync(0xffffffffu, lsum[mf][1], 2);
    }
    __syncthreads();
    if (tg == 0) {
        #pragma unroll
        for (int mf = 0; mf < 4; mf++) {
            int r = rA + mf * 16;
            lpart[wn * QROWS + r]     = lsum[mf][0];
            lpart[wn * QROWS + r + 8] = lsum[mf][1];
        }
    }
    __syncthreads();

    // Epilogue: divide by l, store fp16 (feeds final GEMM)
    #pragma unroll
    for (int mf = 0; mf < 4; mf++) {
        int r0 = rA + mf * 16;
        float li0 = 1.0f / (lpart[r0]     + lpart[QROWS + r0]);
        float li1 = 1.0f / (lpart[r0 + 8] + lpart[QROWS + r0 + 8]);
        int gcol = h * DHEAD + wn * 32 + tg * 2;
        #pragma unroll
        for (int nf = 0; nf < 4; nf++) {
            size_t base0 = ((size_t)(b * LQQ + q0 + r0)) * DMODEL + gcol + nf * 8;
            size_t base1 = ((size_t)(b * LQQ + q0 + r0 + 8)) * DMODEL + gcol + nf * 8;
            *(__half2*)&O[base0] = __floats2half2_rn(oacc[mf][nf][0] * li0,
                                                     oacc[mf][nf][1] * li0);
            *(__half2*)&O[base1] = __floats2half2_rn(oacc[mf][nf][2] * li1,
                                                     oacc[mf][nf][3] * li1);
        }
    }
}

// ---------------------------------------------------------------------------
// Launcher
// ---------------------------------------------------------------------------
extern "C" void kernel_launch(void* const* d_in, const int* in_sizes, int n_in,
                              void* d_out, int out_size) {
    const float* x     = (const float*)d_in[0];
    const float* ctx   = (const float*)d_in[1];
    const void*  mask  = d_in[2];
    const float* lnqw  = (const float*)d_in[3];
    const float* lnqb  = (const float*)d_in[4];
    const float* lncw  = (const float*)d_in[5];
    const float* lncb  = (const float*)d_in[6];
    const float* Wq    = (const float*)d_in[7];
    const float* Wk    = (const float*)d_in[8];
    const float* Wv    = (const float*)d_in[9];
    const float* Wo    = (const float*)d_in[10];
    const float* taup  = (const float*)d_in[11];
    float* out = (float*)d_out;

    __half *qln, *kvln, *q, *k, *vt, *ao, *wq, *wk, *wv, *wo;
    float *maskf;
    cudaGetSymbolAddress((void**)&qln,   g_qln);
    cudaGetSymbolAddress((void**)&kvln,  g_kvln);
    cudaGetSymbolAddress((void**)&q,     g_q);
    cudaGetSymbolAddress((void**)&k,     g_k);
    cudaGetSymbolAddress((void**)&vt,    g_vt);
    cudaGetSymbolAddress((void**)&ao,    g_ao);
    cudaGetSymbolAddress((void**)&maskf, g_maskf);
    cudaGetSymbolAddress((void**)&wq,    g_wq);
    cudaGetSymbolAddress((void**)&wk,    g_wk);
    cudaGetSymbolAddress((void**)&wv,    g_wv);
    cudaGetSymbolAddress((void**)&wo,    g_wo);

    // GEMM dynamic smem (3-stage, halves)
    const int smem_gemm = (int)(6 * ASZH * sizeof(__half));
    cudaFuncSetAttribute(tgemm_kernel, cudaFuncAttributeMaxDynamicSharedMemorySize, smem_gemm);

    // attention dynamic smem
    const int smem_attn = (int)((QROWS * QP + 2 * 64 * QP + 2 * 64 * QP + QROWS * QP)
                                    * sizeof(__half)
                              + (128 + 2 * QROWS) * sizeof(float));
    cudaFuncSetAttribute(attn_kernel, cudaFuncAttributeMaxDynamicSharedMemorySize, smem_attn);

    detect_mask_kernel<<<1, 256>>>((const unsigned char*)mask);
    maskf_kernel<<<(BATCH * LKK + 255) / 256, 256>>>(mask);

    // transpose + fp16-convert weights
    dim3 wtb(32, 8), wtg(DMODEL / 32, DMODEL / 32);
    wtrans_kernel<<<wtg, wtb>>>(Wq, wq);
    wtrans_kernel<<<wtg, wtb>>>(Wk, wk);
    wtrans_kernel<<<wtg, wtb>>>(Wv, wv);
    wtrans_kernel<<<wtg, wtb>>>(Wo, wo);

    ln_kernel<<<BATCH * LQQ, 256>>>(x,   lnqw, lnqb, qln);
    ln_kernel<<<BATCH * LKK, 256>>>(ctx, lncw, lncb, kvln);

    dim3 gg(DMODEL / TBN, (BATCH * LQQ) / TBM);
    tgemm_kernel<<<gg, 256, smem_gemm>>>(qln,  wq, q,  BATCH * LQQ, DMODEL, DMODEL, 0);
    tgemm_kernel<<<gg, 256, smem_gemm>>>(kvln, wk, k,  BATCH * LKK, DMODEL, DMODEL, 0);
    tgemm_kernel<<<gg, 256, smem_gemm>>>(kvln, wv, vt, BATCH * LKK, DMODEL, DMODEL, 1);

    int nvec = BATCH * LQQ * NHEAD;
    l2norm_kernel<<<(nvec * 32) / 256, 256>>>(q, nvec);
    l2norm_kernel<<<(nvec * 32) / 256, 256>>>(k, nvec);

    attn_kernel<<<dim3(LQQ / QROWS, NHEAD, BATCH), 256, smem_attn>>>(q, k, vt, maskf, taup, ao);

    tgemm_kernel<<<gg, 256, smem_gemm>>>(ao, wo, out, BATCH * LQQ, DMODEL, DMODEL, 2);
}

// round 8
// speedup vs baseline: 6.7751x; 1.0776x over previous
#include <cuda_runtime.h>
#include <cuda_fp16.h>
#include <math.h>

// Problem constants
#define BATCH 4
#define LQQ   2048
#define LKK   2048
#define DMODEL 1024
#define NHEAD 16
#define DHEAD 64

// Scratch (static device arrays -- no runtime allocation allowed)
__device__ __half g_qln [BATCH * LQQ * DMODEL];
__device__ __half g_kvln[BATCH * LKK * DMODEL];
__device__ __half g_q   [BATCH * LQQ * DMODEL];
__device__ __half g_k   [BATCH * LKK * DMODEL];
__device__ __half g_vt  [BATCH * NHEAD * DHEAD * LKK];  // [b][h][d][kv]
__device__ __half g_ao  [BATCH * LQQ * DMODEL];
__device__ __half g_wq  [DMODEL * DMODEL];  // transposed [N][K]
__device__ __half g_wk  [DMODEL * DMODEL];
__device__ __half g_wv  [DMODEL * DMODEL];
__device__ __half g_wo  [DMODEL * DMODEL];
__device__ float  g_maskf[BATCH * LKK];   // 0.0 = masked, 1.0 = keep
__device__ int    g_mask_mode;            // 0=uint8, 1=int32, 2=float32

// ---------------------------------------------------------------------------
// mma / cp.async / ldmatrix helpers
// ---------------------------------------------------------------------------
__device__ __forceinline__ void mma_f16(float c[4],
                                        unsigned a0, unsigned a1, unsigned a2, unsigned a3,
                                        unsigned b0, unsigned b1) {
    asm volatile(
        "mma.sync.aligned.m16n8k16.row.col.f32.f16.f16.f32 "
        "{%0,%1,%2,%3},{%4,%5,%6,%7},{%8,%9},{%0,%1,%2,%3};"
        : "+f"(c[0]), "+f"(c[1]), "+f"(c[2]), "+f"(c[3])
        : "r"(a0), "r"(a1), "r"(a2), "r"(a3), "r"(b0), "r"(b1));
}

__device__ __forceinline__ void cp_async16(void* smem_dst, const void* gmem_src) {
    unsigned sa = (unsigned)__cvta_generic_to_shared(smem_dst);
    asm volatile("cp.async.cg.shared.global [%0], [%1], 16;" :: "r"(sa), "l"(gmem_src));
}
__device__ __forceinline__ void cp_commit() {
    asm volatile("cp.async.commit_group;");
}
template <int N>
__device__ __forceinline__ void cp_wait() {
    asm volatile("cp.async.wait_group %0;" :: "n"(N));
}

__device__ __forceinline__ unsigned smem_u32(const void* p) {
    return (unsigned)__cvta_generic_to_shared(p);
}
__device__ __forceinline__ void ldsm4(unsigned& d0, unsigned& d1,
                                      unsigned& d2, unsigned& d3, unsigned saddr) {
    asm volatile("ldmatrix.sync.aligned.m8n8.x4.shared.b16 {%0,%1,%2,%3}, [%4];"
                 : "=r"(d0), "=r"(d1), "=r"(d2), "=r"(d3) : "r"(saddr));
}
__device__ __forceinline__ unsigned packh2(float a, float b) {
    __half2 h = __floats2half2_rn(a, b);
    return *(unsigned*)&h;
}

// ---------------------------------------------------------------------------
// Mask dtype detection (bool array may arrive as u8/i32/f32)
// ---------------------------------------------------------------------------
__global__ void detect_mask_kernel(const unsigned char* __restrict__ m) {
    __shared__ int nz[4];
    if (threadIdx.x < 4) nz[threadIdx.x] = 0;
    __syncthreads();
    int loc = 0;
    for (int i = threadIdx.x; i < 8192; i += blockDim.x)
        if (m[i]) loc = 1;
    if (loc) atomicOr(&nz[threadIdx.x & 3], 1);
    __syncthreads();
    if (threadIdx.x == 0) {
        int mode;
        int tot = nz[0] | nz[1] | nz[2] | nz[3];
        if (!tot)                          mode = 0;
        else if (!(nz[1] | nz[2] | nz[3])) mode = 1; // int32 LE
        else if (!(nz[0] | nz[1]))         mode = 2; // float32 (0x3F800000)
        else                               mode = 0; // uint8/bool
        g_mask_mode = mode;
    }
}

// Convert mask (any dtype) into multiplicative float mask: 0 = masked, 1 = keep
__global__ void maskf_kernel(const void* __restrict__ m) {
    int i = blockIdx.x * blockDim.x + threadIdx.x;
    if (i >= BATCH * LKK) return;
    int mode = g_mask_mode;
    bool mm = (mode == 0) ? (((const unsigned char*)m)[i] != 0)
            : (mode == 1) ? (((const int*)m)[i] != 0)
                          : (((const float*)m)[i] != 0.f);
    g_maskf[i] = mm ? 0.f : 1.f;
}

// ---------------------------------------------------------------------------
// Weight transpose + fp16 convert: W[K][N] f32 -> WT[N][K] half.
// ---------------------------------------------------------------------------
__global__ void wtrans_kernel(const float* __restrict__ W, __half* __restrict__ WT) {
    __shared__ float t[32][33];
    int n0 = blockIdx.x * 32, k0 = blockIdx.y * 32;
    #pragma unroll
    for (int i = 0; i < 4; i++) {
        int k = threadIdx.y + i * 8;
        t[k][threadIdx.x] = W[(size_t)(k0 + k) * DMODEL + n0 + threadIdx.x];
    }
    __syncthreads();
    #pragma unroll
    for (int i = 0; i < 4; i++) {
        int n = threadIdx.y + i * 8;
        WT[(size_t)(n0 + n) * DMODEL + k0 + threadIdx.x] = __float2half(t[threadIdx.x][n]);
    }
}

// ---------------------------------------------------------------------------
// LayerNorm: one block per row of 1024, 256 threads. Output fp16.
// ---------------------------------------------------------------------------
__global__ void ln_kernel(const float* __restrict__ x,
                          const float* __restrict__ w,
                          const float* __restrict__ bia,
                          __half* __restrict__ out) {
    int row = blockIdx.x;
    int tid = threadIdx.x;
    const float4* xr = reinterpret_cast<const float4*>(x + (size_t)row * DMODEL);
    float4 a = xr[tid];
    float s  = a.x + a.y + a.z + a.w;
    float ss = a.x * a.x + a.y * a.y + a.z * a.z + a.w * a.w;

    __shared__ float rs[8], rss[8], stats[2];
    #pragma unroll
    for (int o = 16; o; o >>= 1) {
        s  += __shfl_xor_sync(0xffffffffu, s,  o);
        ss += __shfl_xor_sync(0xffffffffu, ss, o);
    }
    int wid = tid >> 5, lane = tid & 31;
    if (!lane) { rs[wid] = s; rss[wid] = ss; }
    __syncthreads();
    if (tid == 0) {
        float S = 0.f, SS = 0.f;
        #pragma unroll
        for (int i = 0; i < 8; i++) { S += rs[i]; SS += rss[i]; }
        float mean = S * (1.0f / DMODEL);
        float var  = SS * (1.0f / DMODEL) - mean * mean;
        stats[0] = mean;
        stats[1] = rsqrtf(var + 1e-5f);
    }
    __syncthreads();
    float mean = stats[0], rstd = stats[1];
    float4 wv = reinterpret_cast<const float4*>(w)[tid];
    float4 bv = reinterpret_cast<const float4*>(bia)[tid];
    __half2 h0 = __floats2half2_rn((a.x - mean) * rstd * wv.x + bv.x,
                                   (a.y - mean) * rstd * wv.y + bv.y);
    __half2 h1 = __floats2half2_rn((a.z - mean) * rstd * wv.z + bv.z,
                                   (a.w - mean) * rstd * wv.w + bv.w);
    __half2* orow = reinterpret_cast<__half2*>(out + (size_t)row * DMODEL);
    orow[tid * 2]     = h0;
    orow[tid * 2 + 1] = h1;
}

// ---------------------------------------------------------------------------
// fp16 tensor-core GEMM, cp.async 3-stage pipeline, ldmatrix fragment loads.
// C[M,N] = A[M,K] @ BT[N,K]^T. 128x128x32 tiles, 256 threads, warp 64x32.
// mode: 0 = half out, 1 = half transposed-per-head out (g_vt), 2 = float out.
// ---------------------------------------------------------------------------
#define TBM 128
#define TBN 128
#define TBK 32
#define KPAD 40                 // halves per smem row
#define ROWB (KPAD * 2)         // 80 bytes per row
#define ASZH (TBM * KPAD)       // halves per stage per matrix
#define STAGEB (ASZH * 2)       // bytes per stage

__global__ __launch_bounds__(256) void tgemm_kernel(
        const __half* __restrict__ A,
        const __half* __restrict__ BT,
        void* __restrict__ Cout,
        int M, int N, int K, int mode) {
    extern __shared__ __half gsm[];
    __half* As = gsm;              // 3 * ASZH
    __half* Bs = gsm + 3 * ASZH;   // 3 * ASZH

    int tid = threadIdx.x;
    int wid = tid >> 5, lane = tid & 31;
    int wm = wid >> 2, wn = wid & 3;                // 2 x 4 warp grid
    int m0 = blockIdx.y * TBM, n0 = blockIdx.x * TBN;
    int tg = lane & 3;
    int lm = lane >> 3;   // ldmatrix matrix id 0..3
    int lr = lane & 7;    // row within 8x8 matrix

    float acc[4][4][4];
    #pragma unroll
    for (int i = 0; i < 4; i++)
        #pragma unroll
        for (int j = 0; j < 4; j++)
            #pragma unroll
            for (int t = 0; t < 4; t++) acc[i][j][t] = 0.f;

    auto load_tile = [&](int kt, int buf) {
        int k0 = kt * TBK;
        #pragma unroll
        for (int i = 0; i < 2; i++) {
            int cid = tid + i * 256;
            int row = cid >> 2, c8 = (cid & 3) * 8;
            cp_async16(&As[buf * ASZH + row * KPAD + c8],
                       A + (size_t)(m0 + row) * K + k0 + c8);
            cp_async16(&Bs[buf * ASZH + row * KPAD + c8],
                       BT + (size_t)(n0 + row) * K + k0 + c8);
        }
        cp_commit();
    };

    unsigned aoff = (unsigned)((wm * 64 + (lm & 1) * 8 + lr) * ROWB + (lm >> 1) * 16);
    unsigned boff = (unsigned)((wn * 32 + (lm >> 1) * 8 + lr) * ROWB + (lm & 1) * 16);

    unsigned aBase = smem_u32(As) + aoff;
    unsigned bBase = smem_u32(Bs) + boff;

    int nt = K / TBK;
    load_tile(0, 0);
    load_tile(1, 1);

    for (int kt = 0; kt < nt; kt++) {
        int cur = kt % 3;
        if (kt + 2 < nt) cp_wait<1>(); else cp_wait<0>();
        __syncthreads();
        if (kt + 2 < nt) load_tile(kt + 2, (kt + 2) % 3);

        unsigned aS = aBase + cur * STAGEB;
        unsigned bS = bBase + cur * STAGEB;

        #pragma unroll
        for (int ks = 0; ks < 2; ks++) {
            unsigned kofs = ks * 32;   // 8 words = 32 bytes per k16 step
            unsigned af[4][4];
            #pragma unroll
            for (int mf = 0; mf < 4; mf++)
                ldsm4(af[mf][0], af[mf][1], af[mf][2], af[mf][3],
                      aS + kofs + mf * 16 * ROWB);
            unsigned bf[4][2];
            #pragma unroll
            for (int g = 0; g < 2; g++)
                ldsm4(bf[g*2][0], bf[g*2][1], bf[g*2+1][0], bf[g*2+1][1],
                      bS + kofs + g * 16 * ROWB);
            #pragma unroll
            for (int mf = 0; mf < 4; mf++)
                #pragma unroll
                for (int nf = 0; nf < 4; nf++)
                    mma_f16(acc[mf][nf], af[mf][0], af[mf][1], af[mf][2], af[mf][3],
                            bf[nf][0], bf[nf][1]);
        }
    }

    int crow = m0 + wm * 64 + (lane >> 2);
    int ccol = n0 + wn * 32 + tg * 2;
    #pragma unroll
    for (int mf = 0; mf < 4; mf++) {
        #pragma unroll
        for (int nf = 0; nf < 4; nf++) {
            int r = crow + mf * 16;
            int c = ccol + nf * 8;
            float v0 = acc[mf][nf][0], v1 = acc[mf][nf][1];
            float v2 = acc[mf][nf][2], v3 = acc[mf][nf][3];
            if (mode == 0) {
                __half* Ch = (__half*)Cout;
                *(__half2*)&Ch[(size_t)r * N + c]       = __floats2half2_rn(v0, v1);
                *(__half2*)&Ch[(size_t)(r + 8) * N + c] = __floats2half2_rn(v2, v3);
            } else if (mode == 2) {
                float* Cf = (float*)Cout;
                *(float2*)&Cf[(size_t)r * N + c]       = make_float2(v0, v1);
                *(float2*)&Cf[(size_t)(r + 8) * N + c] = make_float2(v2, v3);
            } else {
                // transposed-per-head store into g_vt[b][n][kv], n = h*64+d
                __half* vt = (__half*)Cout;
                int bb0 = r >> 11, kv0 = r & 2047;
                int bb1 = (r + 8) >> 11, kv1 = (r + 8) & 2047;
                vt[((size_t)(bb0 * 1024 + c)) * 2048 + kv0]     = __float2half(v0);
                vt[((size_t)(bb0 * 1024 + c + 1)) * 2048 + kv0] = __float2half(v1);
                vt[((size_t)(bb1 * 1024 + c)) * 2048 + kv1]     = __float2half(v2);
                vt[((size_t)(bb1 * 1024 + c + 1)) * 2048 + kv1] = __float2half(v3);
            }
        }
    }
}

// ---------------------------------------------------------------------------
// L2 norm over contiguous 64-half head vectors: one warp per vector.
// ---------------------------------------------------------------------------
__global__ void l2norm_kernel(__half* __restrict__ d, int nvec) {
    int idx  = blockIdx.x * blockDim.x + threadIdx.x;
    int warp = idx >> 5;
    int lane = idx & 31;
    if (warp >= nvec) return;
    __half2* p = reinterpret_cast<__half2*>(d) + (size_t)warp * 32 + lane;
    float2 f = __half22float2(*p);
    float ss = f.x * f.x + f.y * f.y;
    #pragma unroll
    for (int o = 16; o; o >>= 1) ss += __shfl_xor_sync(0xffffffffu, ss, o);
    float sc = 1.0f / fmaxf(sqrtf(ss), 1e-12f);
    *p = __floats2half2_rn(f.x * sc, f.y * sc);
}

// ---------------------------------------------------------------------------
// Flash attention, fp16 mma + ldmatrix, fixed-max softmax, FA2 register P.
// 8 warps split on m only: warp tile 32 q-rows x 64 kv-cols. P stays in
// registers (S-accum layout == A-operand layout of PV mma). One sync/tile.
// Q[m][64] half, K[kv][64] half, Vt[d][kv] half (pre-transposed per head).
// Grid (LQ/256, H, B), 256 threads.
// ---------------------------------------------------------------------------
#define QROWS 256
#define QP 72       // halves per smem row
#define QROWB (QP * 2)   // 144 bytes

__global__ __launch_bounds__(256) void attn_kernel(
        const __half* __restrict__ Q,
        const __half* __restrict__ Kp,
        const __half* __restrict__ Vt,
        const float* __restrict__ maskf,
        const float* __restrict__ tau_p,
        __half* __restrict__ O) {
    extern __shared__ __half smh[];
    __half* Qs = smh;                    // QROWS*QP
    __half* Ks = Qs + QROWS * QP;        // 2 * 64*QP
    __half* Vs = Ks + 2 * 64 * QP;       // 2 * 64*QP
    float*  Ms = (float*)(Vs + 2 * 64 * QP);  // 2 * 64

    int tid  = threadIdx.x;
    int wid  = tid >> 5, lane = tid & 31;
    int q0   = blockIdx.x * QROWS;
    int h    = blockIdx.y;
    int b    = blockIdx.z;
    int tg   = lane & 3;
    int lm   = lane >> 3;
    int lr   = lane & 7;

    float inv_tau = 1.0f / (*tau_p + 1e-6f);
    float MFIX = fabsf(inv_tau);   // scores bounded by |1/tau| (unit q,k)

    const __half* Qbase = Q  + ((size_t)(b * LQQ + q0)) * DMODEL + h * DHEAD;
    const __half* Kbase = Kp + ((size_t)b * LKK) * DMODEL + h * DHEAD;
    const __half* Vbase = Vt + ((size_t)(b * 1024 + h * DHEAD)) * 2048;  // rows = d
    const float*  Mbase = maskf + (size_t)b * LKK;

    // Q tile: 256 rows x 64 halves = 2048 16B-chunks, 8 per thread
    #pragma unroll
    for (int i = 0; i < 8; i++) {
        int cid = tid + i * 256;
        int r = cid >> 3, c8 = (cid & 7) * 8;
        cp_async16(&Qs[r * QP + c8], Qbase + (size_t)r * DMODEL + c8);
    }
    cp_commit();

    auto load_kv = [&](int k0, int buf) {
        #pragma unroll
        for (int i = 0; i < 2; i++) {
            int cid = tid + i * 256;
            int r = cid >> 3, c8 = (cid & 7) * 8;
            cp_async16(&Ks[buf * 64 * QP + r * QP + c8],
                       Kbase + (size_t)(k0 + r) * DMODEL + c8);
            cp_async16(&Vs[buf * 64 * QP + r * QP + c8],
                       Vbase + (size_t)r * 2048 + k0 + c8);
        }
        if (tid < 16) cp_async16(&Ms[buf * 64 + tid * 4], Mbase + k0 + tid * 4);
        cp_commit();
    };

    load_kv(0, 0);

    float oacc[2][8][4];
    #pragma unroll
    for (int m = 0; m < 2; m++)
        #pragma unroll
        for (int i = 0; i < 8; i++)
            #pragma unroll
            for (int j = 0; j < 4; j++) oacc[m][i][j] = 0.f;
    float lsum[2][2] = {};

    // ldmatrix lane base offsets
    unsigned aoff = (unsigned)((wid * 32 + (lm & 1) * 8 + lr) * QROWB + (lm >> 1) * 16);
    unsigned boff = (unsigned)(((lm >> 1) * 8 + lr) * QROWB + (lm & 1) * 16);
    unsigned qA = smem_u32(Qs) + aoff;
    unsigned kB = smem_u32(Ks) + boff;
    unsigned vB = smem_u32(Vs) + boff;
    const unsigned KVSTAGE = 64 * QP * 2;  // bytes per KV buffer

    const int NT = LKK / 64;
    for (int kt = 0; kt < NT; kt++) {
        int cur = kt & 1;
        cp_wait<0>();
        __syncthreads();
        if (kt + 1 < NT) load_kv((kt + 1) * 64, cur ^ 1);

        unsigned kS = kB + cur * KVSTAGE;
        unsigned vS = vB + cur * KVSTAGE;
        const float* Msb = Ms + cur * 64;

        // S = Q . K^T  (per warp: 32 rows x 64 cols), 4 k16 steps
        float sacc[2][8][4];
        #pragma unroll
        for (int m = 0; m < 2; m++)
            #pragma unroll
            for (int i = 0; i < 8; i++)
                #pragma unroll
                for (int j = 0; j < 4; j++) sacc[m][i][j] = 0.f;

        #pragma unroll
        for (int ks = 0; ks < 4; ks++) {
            unsigned kofs = ks * 32;
            unsigned bf[8][2];
            #pragma unroll
            for (int g = 0; g < 4; g++)
                ldsm4(bf[g*2][0], bf[g*2][1], bf[g*2+1][0], bf[g*2+1][1],
                      kS + kofs + g * 16 * QROWB);
            #pragma unroll
            for (int mf = 0; mf < 2; mf++) {
                unsigned a0, a1, a2, a3;
                ldsm4(a0, a1, a2, a3, qA + kofs + mf * 16 * QROWB);
                #pragma unroll
                for (int nf = 0; nf < 8; nf++)
                    mma_f16(sacc[mf][nf], a0, a1, a2, a3, bf[nf][0], bf[nf][1]);
            }
        }

        // softmax (fixed max) + mask; P packed to registers (A-operand layout)
        unsigned ph[2][8][2];
        #pragma unroll
        for (int mf = 0; mf < 2; mf++) {
            #pragma unroll
            for (int nf = 0; nf < 8; nf++) {
                int c = nf * 8 + tg * 2;
                float mk0 = Msb[c], mk1 = Msb[c + 1];
                float p00 = __expf(fminf(sacc[mf][nf][0] * inv_tau - MFIX, 0.f)) * mk0;
                float p01 = __expf(fminf(sacc[mf][nf][1] * inv_tau - MFIX, 0.f)) * mk1;
                float p10 = __expf(fminf(sacc[mf][nf][2] * inv_tau - MFIX, 0.f)) * mk0;
                float p11 = __expf(fminf(sacc[mf][nf][3] * inv_tau - MFIX, 0.f)) * mk1;
                lsum[mf][0] += p00 + p01;
                lsum[mf][1] += p10 + p11;
                ph[mf][nf][0] = packh2(p00, p01);   // rows lane/4
                ph[mf][nf][1] = packh2(p10, p11);   // rows lane/4 + 8
            }
        }

        // O += P . V   (A = P regs, B = Vt[d][kv] fragments)
        #pragma unroll
        for (int ks = 0; ks < 4; ks++) {
            unsigned kofs = ks * 32;
            unsigned bf[8][2];
            #pragma unroll
            for (int g = 0; g < 4; g++)
                ldsm4(bf[g*2][0], bf[g*2][1], bf[g*2+1][0], bf[g*2+1][1],
                      vS + kofs + g * 16 * QROWB);
            #pragma unroll
            for (int mf = 0; mf < 2; mf++) {
                unsigned a0 = ph[mf][2*ks][0];
                unsigned a1 = ph[mf][2*ks][1];
                unsigned a2 = ph[mf][2*ks+1][0];
                unsigned a3 = ph[mf][2*ks+1][1];
                #pragma unroll
                for (int nf = 0; nf < 8; nf++)
                    mma_f16(oacc[mf][nf], a0, a1, a2, a3, bf[nf][0], bf[nf][1]);
            }
        }
    }

    // row sums: quad-reduce (each warp owns full rows)
    #pragma unroll
    for (int mf = 0; mf < 2; mf++) {
        lsum[mf][0] += __shfl_xor_sync(0xffffffffu, lsum[mf][0], 1);
        lsum[mf][0] += __shfl_xor_sync(0xffffffffu, lsum[mf][0], 2);
        lsum[mf][1] += __shfl_xor_sync(0xffffffffu, lsum[mf][1], 1);
        lsum[mf][1] += __shfl_xor_sync(0xffffffffu, lsum[mf][1], 2);
    }

    // Epilogue: divide by l, store fp16 (feeds final GEMM)
    int rA = wid * 32 + (lane >> 2);
    #pragma unroll
    for (int mf = 0; mf < 2; mf++) {
        int r0 = rA + mf * 16;
        float li0 = 1.0f / lsum[mf][0];
        float li1 = 1.0f / lsum[mf][1];
        int gcol = h * DHEAD + tg * 2;
        #pragma unroll
        for (int nf = 0; nf < 8; nf++) {
            size_t base0 = ((size_t)(b * LQQ + q0 + r0)) * DMODEL + gcol + nf * 8;
            size_t base1 = ((size_t)(b * LQQ + q0 + r0 + 8)) * DMODEL + gcol + nf * 8;
            *(__half2*)&O[base0] = __floats2half2_rn(oacc[mf][nf][0] * li0,
                                                     oacc[mf][nf][1] * li0);
            *(__half2*)&O[base1] = __floats2half2_rn(oacc[mf][nf][2] * li1,
                                                     oacc[mf][nf][3] * li1);
        }
    }
}

// ---------------------------------------------------------------------------
// Launcher
// ---------------------------------------------------------------------------
extern "C" void kernel_launch(void* const* d_in, const int* in_sizes, int n_in,
                              void* d_out, int out_size) {
    const float* x     = (const float*)d_in[0];
    const float* ctx   = (const float*)d_in[1];
    const void*  mask  = d_in[2];
    const float* lnqw  = (const float*)d_in[3];
    const float* lnqb  = (const float*)d_in[4];
    const float* lncw  = (const float*)d_in[5];
    const float* lncb  = (const float*)d_in[6];
    const float* Wq    = (const float*)d_in[7];
    const float* Wk    = (const float*)d_in[8];
    const float* Wv    = (const float*)d_in[9];
    const float* Wo    = (const float*)d_in[10];
    const float* taup  = (const float*)d_in[11];
    float* out = (float*)d_out;

    __half *qln, *kvln, *q, *k, *vt, *ao, *wq, *wk, *wv, *wo;
    float *maskf;
    cudaGetSymbolAddress((void**)&qln,   g_qln);
    cudaGetSymbolAddress((void**)&kvln,  g_kvln);
    cudaGetSymbolAddress((void**)&q,     g_q);
    cudaGetSymbolAddress((void**)&k,     g_k);
    cudaGetSymbolAddress((void**)&vt,    g_vt);
    cudaGetSymbolAddress((void**)&ao,    g_ao);
    cudaGetSymbolAddress((void**)&maskf, g_maskf);
    cudaGetSymbolAddress((void**)&wq,    g_wq);
    cudaGetSymbolAddress((void**)&wk,    g_wk);
    cudaGetSymbolAddress((void**)&wv,    g_wv);
    cudaGetSymbolAddress((void**)&wo,    g_wo);

    // GEMM dynamic smem (3-stage, halves)
    const int smem_gemm = (int)(6 * ASZH * sizeof(__half));
    cudaFuncSetAttribute(tgemm_kernel, cudaFuncAttributeMaxDynamicSharedMemorySize, smem_gemm);

    // attention dynamic smem (no P buffer)
    const int smem_attn = (int)((QROWS * QP + 2 * 64 * QP + 2 * 64 * QP) * sizeof(__half)
                              + 128 * sizeof(float));
    cudaFuncSetAttribute(attn_kernel, cudaFuncAttributeMaxDynamicSharedMemorySize, smem_attn);

    detect_mask_kernel<<<1, 256>>>((const unsigned char*)mask);
    maskf_kernel<<<(BATCH * LKK + 255) / 256, 256>>>(mask);

    // transpose + fp16-convert weights
    dim3 wtb(32, 8), wtg(DMODEL / 32, DMODEL / 32);
    wtrans_kernel<<<wtg, wtb>>>(Wq, wq);
    wtrans_kernel<<<wtg, wtb>>>(Wk, wk);
    wtrans_kernel<<<wtg, wtb>>>(Wv, wv);
    wtrans_kernel<<<wtg, wtb>>>(Wo, wo);

    ln_kernel<<<BATCH * LQQ, 256>>>(x,   lnqw, lnqb, qln);
    ln_kernel<<<BATCH * LKK, 256>>>(ctx, lncw, lncb, kvln);

    dim3 gg(DMODEL / TBN, (BATCH * LQQ) / TBM);
    tgemm_kernel<<<gg, 256, smem_gemm>>>(qln,  wq, q,  BATCH * LQQ, DMODEL, DMODEL, 0);
    tgemm_kernel<<<gg, 256, smem_gemm>>>(kvln, wk, k,  BATCH * LKK, DMODEL, DMODEL, 0);
    tgemm_kernel<<<gg, 256, smem_gemm>>>(kvln, wv, vt, BATCH * LKK, DMODEL, DMODEL, 1);

    int nvec = BATCH * LQQ * NHEAD;
    l2norm_kernel<<<(nvec * 32) / 256, 256>>>(q, nvec);
    l2norm_kernel<<<(nvec * 32) / 256, 256>>>(k, nvec);

    attn_kernel<<<dim3(LQQ / QROWS, NHEAD, BATCH), 256, smem_attn>>>(q, k, vt, maskf, taup, ao);

    tgemm_kernel<<<gg, 256, smem_gemm>>>(ao, wo, out, BATCH * LQQ, DMODEL, DMODEL, 2);
}